// round 2
// baseline (speedup 1.0000x reference)
#include <cuda_runtime.h>
#include <math.h>

// Problem constants
#define Ssz 1024
#define Bsz 4
#define Esz 1024
#define Hsz 16
#define Msz 128
#define Vsz 64
#define NCOLS (Hsz * (2 * Msz + Vsz))   // 5120 combined q/k/v output columns
#define SBE (Ssz * Bsz * Esz)           // 4194304

// Scratch (allocation-free rule: static __device__ arrays)
__device__ float2 g_q[Bsz * Hsz * Ssz * Msz];    // (b,h,s,m)
__device__ float2 g_k[Bsz * Hsz * Ssz * Msz];
__device__ float2 g_v[Bsz * Hsz * Ssz * Vsz];    // (b,h,s,v)
__device__ float2 g_upd[Ssz * Bsz * Esz];        // (s,b,h*V+v)

// ---------------------------------------------------------------------------
// Kernel 1: fused complex QKV projection.
// C[r,c] = sum_e x[r,e] * W[c,e] (complex), r = s*B+b (4096), c in [0,5120).
// 64x64 tile, 16 K-chunk, 256 threads, 4x4 complex micro-tile.
// ---------------------------------------------------------------------------
__global__ __launch_bounds__(256) void proj_gemm(
    const float* __restrict__ xre, const float* __restrict__ xim,
    const float* __restrict__ wq_re, const float* __restrict__ wq_im,
    const float* __restrict__ wk_re, const float* __restrict__ wk_im,
    const float* __restrict__ wv_re, const float* __restrict__ wv_im)
{
    __shared__ float2 As[16][66];
    __shared__ float2 Bs[16][66];
    __shared__ const float* rowRe[64];
    __shared__ const float* rowIm[64];

    const int rowBase = blockIdx.x * 64;
    const int colBase = blockIdx.y * 64;
    const int tid = threadIdx.x;

    if (tid < 64) {
        int c = colBase + tid;
        int h = c / 320;
        int j = c % 320;
        const float* re;
        const float* im;
        if (j < Msz) {
            re = wq_re + (h * Msz + j) * Esz;
            im = wq_im + (h * Msz + j) * Esz;
        } else if (j < 2 * Msz) {
            re = wk_re + (h * Msz + (j - Msz)) * Esz;
            im = wk_im + (h * Msz + (j - Msz)) * Esz;
        } else {
            re = wv_re + (h * Vsz + (j - 2 * Msz)) * Esz;
            im = wv_im + (h * Vsz + (j - 2 * Msz)) * Esz;
        }
        rowRe[tid] = re;
        rowIm[tid] = im;
    }
    __syncthreads();

    const int tx = tid & 15;
    const int ty = tid >> 4;
    const int lrow = tid >> 2;        // 0..63 : which tile row/col this thread loads
    const int lkq  = (tid & 3) * 4;   // 0,4,8,12 : k offset within chunk

    const float* aRe = xre + (rowBase + lrow) * Esz + lkq;
    const float* aIm = xim + (rowBase + lrow) * Esz + lkq;
    const float* bRe = rowRe[lrow] + lkq;
    const float* bIm = rowIm[lrow] + lkq;

    float2 acc[4][4];
#pragma unroll
    for (int i = 0; i < 4; ++i)
#pragma unroll
        for (int j = 0; j < 4; ++j) acc[i][j] = make_float2(0.f, 0.f);

    for (int kk = 0; kk < Esz; kk += 16) {
        float4 ar = *(const float4*)(aRe + kk);
        float4 ai = *(const float4*)(aIm + kk);
        float4 br = *(const float4*)(bRe + kk);
        float4 bi = *(const float4*)(bIm + kk);
        As[lkq + 0][lrow] = make_float2(ar.x, ai.x);
        As[lkq + 1][lrow] = make_float2(ar.y, ai.y);
        As[lkq + 2][lrow] = make_float2(ar.z, ai.z);
        As[lkq + 3][lrow] = make_float2(ar.w, ai.w);
        Bs[lkq + 0][lrow] = make_float2(br.x, bi.x);
        Bs[lkq + 1][lrow] = make_float2(br.y, bi.y);
        Bs[lkq + 2][lrow] = make_float2(br.z, bi.z);
        Bs[lkq + 3][lrow] = make_float2(br.w, bi.w);
        __syncthreads();

#pragma unroll
        for (int k = 0; k < 16; ++k) {
            float4 a0 = *(const float4*)&As[k][ty * 4];
            float4 a1 = *(const float4*)&As[k][ty * 4 + 2];
            float4 b0 = *(const float4*)&Bs[k][tx * 4];
            float4 b1 = *(const float4*)&Bs[k][tx * 4 + 2];
            float2 a[4] = { {a0.x, a0.y}, {a0.z, a0.w}, {a1.x, a1.y}, {a1.z, a1.w} };
            float2 b[4] = { {b0.x, b0.y}, {b0.z, b0.w}, {b1.x, b1.y}, {b1.z, b1.w} };
#pragma unroll
            for (int i = 0; i < 4; ++i)
#pragma unroll
                for (int j = 0; j < 4; ++j) {
                    acc[i][j].x = fmaf(a[i].x, b[j].x, acc[i][j].x);
                    acc[i][j].x = fmaf(-a[i].y, b[j].y, acc[i][j].x);
                    acc[i][j].y = fmaf(a[i].x, b[j].y, acc[i][j].y);
                    acc[i][j].y = fmaf(a[i].y, b[j].x, acc[i][j].y);
                }
        }
        __syncthreads();
    }

#pragma unroll
    for (int j = 0; j < 4; ++j) {
        int c = colBase + tx * 4 + j;
        int h = c / 320;
        int jj = c % 320;
#pragma unroll
        for (int i = 0; i < 4; ++i) {
            int r = rowBase + ty * 4 + i;
            int s = r >> 2;
            int b = r & 3;
            float2 val = acc[i][j];
            if (jj < Msz)
                g_q[((b * Hsz + h) * Ssz + s) * Msz + jj] = val;
            else if (jj < 2 * Msz)
                g_k[((b * Hsz + h) * Ssz + s) * Msz + (jj - Msz)] = val;
            else
                g_v[((b * Hsz + h) * Ssz + s) * Vsz + (jj - 2 * Msz)] = val;
        }
    }
}

// ---------------------------------------------------------------------------
// Kernel 2: causal complex attention with |score| softmax (flash-style).
// Block: 1024 threads = 32 warps, each warp owns one query row of a 32-row
// tile. Grid (S/32, B*H). Online softmax over key tiles of 32.
// ---------------------------------------------------------------------------
__global__ __launch_bounds__(1024) void attn_kernel()
{
    extern __shared__ char smraw[];
    float2* q_s = (float2*)smraw;            // [32][128]
    float2* k_s = q_s + 32 * 128;            // [128][33]  (transposed, padded)
    float2* v_s = k_s + 128 * 33;            // [32][64]

    const int tile = blockIdx.x;             // 0..31
    const int bh = blockIdx.y;               // b*H+h, 0..63
    const int warp = threadIdx.x >> 5;
    const int lane = threadIdx.x & 31;
    const int srow = tile * 32 + warp;

    const float2* qbase = g_q + ((long)bh * Ssz + tile * 32) * Msz;
    for (int i = threadIdx.x; i < 32 * 128; i += 1024)
        q_s[i] = qbase[i];                   // q_s[row][m], row-major 128

    float run_max = -INFINITY;
    float run_sum = 0.f;
    float2 acc0 = make_float2(0.f, 0.f);
    float2 acc1 = make_float2(0.f, 0.f);
    const float inv_sqrt_m = 0.088388347648318447f;   // 1/sqrt(128)

    for (int kt = 0; kt <= tile; ++kt) {
        const float2* kbase = g_k + ((long)bh * Ssz + kt * 32) * Msz;
        for (int i = threadIdx.x; i < 32 * 128; i += 1024) {
            int t = i >> 7, m = i & 127;
            k_s[m * 33 + t] = kbase[i];
        }
        const float2* vbase = g_v + ((long)bh * Ssz + kt * 32) * Vsz;
        for (int i = threadIdx.x; i < 32 * 64; i += 1024)
            v_s[i] = vbase[i];
        __syncthreads();

        // complex dot: score(row srow, key kt*32+lane)
        float sr = 0.f, si = 0.f;
        const float2* qrow = q_s + warp * 128;
#pragma unroll 8
        for (int m = 0; m < 128; ++m) {
            float2 qv = qrow[m];
            float2 kv = k_s[m * 33 + lane];
            sr = fmaf(qv.x, kv.x, sr);
            sr = fmaf(-qv.y, kv.y, sr);
            si = fmaf(qv.x, kv.y, si);
            si = fmaf(qv.y, kv.x, si);
        }
        int tcol = kt * 32 + lane;
        float amp = (tcol <= srow) ? sqrtf(sr * sr + si * si) * inv_sqrt_m
                                   : -INFINITY;
        // warp-wide online softmax
        float tmax = amp;
#pragma unroll
        for (int o = 16; o > 0; o >>= 1)
            tmax = fmaxf(tmax, __shfl_xor_sync(0xffffffffu, tmax, o));
        float nmax = fmaxf(run_max, tmax);
        float corr = __expf(run_max - nmax);      // run_max=-inf,nmax finite -> 0
        float p = __expf(amp - nmax);             // amp=-inf -> 0
        float psum = p;
#pragma unroll
        for (int o = 16; o > 0; o >>= 1)
            psum += __shfl_xor_sync(0xffffffffu, psum, o);
        run_sum = run_sum * corr + psum;
        run_max = nmax;
        acc0.x *= corr; acc0.y *= corr;
        acc1.x *= corr; acc1.y *= corr;

#pragma unroll
        for (int t = 0; t < 32; ++t) {
            float pt = __shfl_sync(0xffffffffu, p, t);
            float2 v0 = v_s[t * 64 + lane];
            float2 v1 = v_s[t * 64 + lane + 32];
            acc0.x = fmaf(pt, v0.x, acc0.x);
            acc0.y = fmaf(pt, v0.y, acc0.y);
            acc1.x = fmaf(pt, v1.x, acc1.x);
            acc1.y = fmaf(pt, v1.y, acc1.y);
        }
        __syncthreads();
    }

    float inv = 1.0f / run_sum;
    int b = bh >> 4;     // H = 16
    int h = bh & 15;
    long base = ((long)srow * Bsz + b) * Esz + h * Vsz;
    g_upd[base + lane]      = make_float2(acc0.x * inv, acc0.y * inv);
    g_upd[base + lane + 32] = make_float2(acc1.x * inv, acc1.y * inv);
}

// ---------------------------------------------------------------------------
// Kernel 3: output projection + residual.
// out[r,f] = sum_e upd[r,e] * wo[e,f] + x[r,f]  (complex);
// output stacked: real block then imag block.
// ---------------------------------------------------------------------------
__global__ __launch_bounds__(256) void out_gemm(
    const float* __restrict__ wo_re, const float* __restrict__ wo_im,
    const float* __restrict__ xre, const float* __restrict__ xim,
    float* __restrict__ out)
{
    __shared__ float2 As[16][66];
    __shared__ float2 Bs[16][66];

    const int rowBase = blockIdx.x * 64;
    const int colBase = blockIdx.y * 64;
    const int tid = threadIdx.x;
    const int tx = tid & 15;
    const int ty = tid >> 4;

    // A loader: 4 threads per row, each 4 complex elems
    const int lrow = tid >> 2;
    const int lkq  = (tid & 3) * 4;
    const float2* aP = g_upd + (long)(rowBase + lrow) * Esz + lkq;

    // B loader: thread -> (k = tid>>4, f quad = (tid&15)*4)
    const int lk = tid >> 4;
    const int lf = (tid & 15) * 4;

    float2 acc[4][4];
#pragma unroll
    for (int i = 0; i < 4; ++i)
#pragma unroll
        for (int j = 0; j < 4; ++j) acc[i][j] = make_float2(0.f, 0.f);

    for (int kk = 0; kk < Esz; kk += 16) {
        float4 a01 = *(const float4*)(aP + kk);       // complex lkq, lkq+1
        float4 a23 = *(const float4*)(aP + kk + 2);   // complex lkq+2, lkq+3
        As[lkq + 0][lrow] = make_float2(a01.x, a01.y);
        As[lkq + 1][lrow] = make_float2(a01.z, a01.w);
        As[lkq + 2][lrow] = make_float2(a23.x, a23.y);
        As[lkq + 3][lrow] = make_float2(a23.z, a23.w);

        float4 br = *(const float4*)(wo_re + (long)(kk + lk) * Esz + colBase + lf);
        float4 bi = *(const float4*)(wo_im + (long)(kk + lk) * Esz + colBase + lf);
        Bs[lk][lf + 0] = make_float2(br.x, bi.x);
        Bs[lk][lf + 1] = make_float2(br.y, bi.y);
        Bs[lk][lf + 2] = make_float2(br.z, bi.z);
        Bs[lk][lf + 3] = make_float2(br.w, bi.w);
        __syncthreads();

#pragma unroll
        for (int k = 0; k < 16; ++k) {
            float4 a0 = *(const float4*)&As[k][ty * 4];
            float4 a1 = *(const float4*)&As[k][ty * 4 + 2];
            float4 b0 = *(const float4*)&Bs[k][tx * 4];
            float4 b1 = *(const float4*)&Bs[k][tx * 4 + 2];
            float2 a[4] = { {a0.x, a0.y}, {a0.z, a0.w}, {a1.x, a1.y}, {a1.z, a1.w} };
            float2 b[4] = { {b0.x, b0.y}, {b0.z, b0.w}, {b1.x, b1.y}, {b1.z, b1.w} };
#pragma unroll
            for (int i = 0; i < 4; ++i)
#pragma unroll
                for (int j = 0; j < 4; ++j) {
                    acc[i][j].x = fmaf(a[i].x, b[j].x, acc[i][j].x);
                    acc[i][j].x = fmaf(-a[i].y, b[j].y, acc[i][j].x);
                    acc[i][j].y = fmaf(a[i].x, b[j].y, acc[i][j].y);
                    acc[i][j].y = fmaf(a[i].y, b[j].x, acc[i][j].y);
                }
        }
        __syncthreads();
    }

#pragma unroll
    for (int i = 0; i < 4; ++i) {
        int r = rowBase + ty * 4 + i;
#pragma unroll
        for (int j = 0; j < 4; ++j) {
            int c = colBase + tx * 4 + j;
            long idx = (long)r * Esz + c;
            out[idx]       = acc[i][j].x + xre[idx];
            out[SBE + idx] = acc[i][j].y + xim[idx];
        }
    }
}

// ---------------------------------------------------------------------------
extern "C" void kernel_launch(void* const* d_in, const int* in_sizes, int n_in,
                              void* d_out, int out_size)
{
    const float* logits_re = (const float*)d_in[0];
    const float* logits_im = (const float*)d_in[1];
    const float* wq_re = (const float*)d_in[2];
    const float* wq_im = (const float*)d_in[3];
    const float* wk_re = (const float*)d_in[4];
    const float* wk_im = (const float*)d_in[5];
    const float* wv_re = (const float*)d_in[6];
    const float* wv_im = (const float*)d_in[7];
    const float* wo_re = (const float*)d_in[8];
    const float* wo_im = (const float*)d_in[9];
    float* out = (float*)d_out;

    // QKV projection: rows 4096/64=64, cols 5120/64=80
    proj_gemm<<<dim3(64, 80), 256>>>(logits_re, logits_im,
                                     wq_re, wq_im, wk_re, wk_im, wv_re, wv_im);

    // Attention: 32 query tiles x 64 (b,h)
    const int attn_smem = (32 * 128 + 128 * 33 + 32 * 64) * (int)sizeof(float2);
    static bool attr_set = false;
    if (!attr_set) {
        cudaFuncSetAttribute(attn_kernel,
                             cudaFuncAttributeMaxDynamicSharedMemorySize,
                             attn_smem);
        attr_set = true;
    }
    attn_kernel<<<dim3(32, 64), 1024, attn_smem>>>();

    // Output projection + residual: rows 64, cols 1024/64=16
    out_gemm<<<dim3(64, 16), 256>>>(wo_re, wo_im, logits_re, logits_im, out);
}

// round 4
// speedup vs baseline: 1.3702x; 1.3702x over previous
#include <cuda_runtime.h>
#include <cuda_bf16.h>
#include <cstdint>
#include <math.h>

#define Ssz 1024
#define Bsz 4
#define Esz 1024
#define Hsz 16
#define Msz 128
#define Vsz 64
#define SBE (Ssz * Bsz * Esz)      // 4194304
#define GK  6144                   // packed K = 6 * 1024
#define NCHUNK (GK / 32)           // 192 K-chunks of 32

// ---------------- scratch (static device globals; no allocs) ----------------
__device__ float2 g_q[Bsz * Hsz * Ssz * Msz];
__device__ float2 g_k[Bsz * Hsz * Ssz * Msz];
__device__ float2 g_v[Bsz * Hsz * Ssz * Vsz];
__device__ float2 g_upd[Ssz * Bsz * Esz];
__device__ __align__(16) __nv_bfloat16 g_Aproj[4096 * GK];
__device__ __align__(16) __nv_bfloat16 g_Bproj[10240 * GK];
__device__ __align__(16) __nv_bfloat16 g_Bout [2048 * GK];
__device__ __align__(16) __nv_bfloat16 g_Aatt [4096 * GK];

// ---------------- helpers ----------------------------------------------------
__device__ __forceinline__ uint32_t smem_u32(const void* p) {
    uint32_t a;
    asm("{ .reg .u64 t; cvta.to.shared.u64 t, %1; cvt.u32.u64 %0, t; }"
        : "=r"(a) : "l"(p));
    return a;
}
__device__ __forceinline__ void cp_async16(uint32_t dst, const void* src) {
    asm volatile("cp.async.cg.shared.global [%0], [%1], 16;"
                 :: "r"(dst), "l"(src) : "memory");
}
#define CP_COMMIT() asm volatile("cp.async.commit_group;" ::: "memory")
#define CP_WAIT2()  asm volatile("cp.async.wait_group 2;" ::: "memory")

__device__ __forceinline__ void ldsm_x4(uint32_t& r0, uint32_t& r1,
                                        uint32_t& r2, uint32_t& r3, uint32_t a) {
    asm volatile("ldmatrix.sync.aligned.m8n8.x4.shared.b16 {%0,%1,%2,%3}, [%4];"
                 : "=r"(r0), "=r"(r1), "=r"(r2), "=r"(r3) : "r"(a));
}
__device__ __forceinline__ void mma_bf16(float* d, const uint32_t* a,
                                         const uint32_t* b) {
    asm volatile(
        "mma.sync.aligned.m16n8k16.row.col.f32.bf16.bf16.f32 "
        "{%0,%1,%2,%3}, {%4,%5,%6,%7}, {%8,%9}, {%0,%1,%2,%3};"
        : "+f"(d[0]), "+f"(d[1]), "+f"(d[2]), "+f"(d[3])
        : "r"(a[0]), "r"(a[1]), "r"(a[2]), "r"(a[3]), "r"(b[0]), "r"(b[1]));
}

__device__ __forceinline__ void split_bf16(float x, __nv_bfloat16& h, __nv_bfloat16& l) {
    h = __float2bfloat16(x);
    l = __float2bfloat16(x - __bfloat162float(h));
}

// ---------------- pack kernels ----------------------------------------------
__global__ __launch_bounds__(256) void pack_A_proj(
    const float* __restrict__ xre, const float* __restrict__ xim)
{
    int idx = blockIdx.x * 256 + threadIdx.x;
    int r = idx >> 10, e = idx & 1023;
    __nv_bfloat16 rh, rl, ih, il;
    split_bf16(xre[idx], rh, rl);
    split_bf16(xim[idx], ih, il);
    __nv_bfloat16* p = g_Aproj + (size_t)r * GK + e;
    p[0] = rh; p[1024] = rh; p[2048] = rl;
    p[3072] = ih; p[4096] = ih; p[5120] = il;
}

__global__ __launch_bounds__(256) void pack_A_att()
{
    int idx = blockIdx.x * 256 + threadIdx.x;
    int r = idx >> 10, e = idx & 1023;
    float2 u = g_upd[idx];
    __nv_bfloat16 rh, rl, ih, il;
    split_bf16(u.x, rh, rl);
    split_bf16(u.y, ih, il);
    __nv_bfloat16* p = g_Aatt + (size_t)r * GK + e;
    p[0] = rh; p[1024] = rh; p[2048] = rl;
    p[3072] = ih; p[4096] = ih; p[5120] = il;
}

__device__ __forceinline__ void write_B_rows(__nv_bfloat16* base, size_t n_re,
                                             int e, float wr, float wi)
{
    __nv_bfloat16 rh, rl, ih, il;
    split_bf16(wr, rh, rl);
    split_bf16(wi, ih, il);
    __nv_bfloat16 nih = __float2bfloat16(-__bfloat162float(ih));
    __nv_bfloat16 nil = __float2bfloat16(-__bfloat162float(il));
    __nv_bfloat16* pr = base + n_re * GK + e;          // real-out row
    pr[0] = rh; pr[1024] = rl; pr[2048] = rh;
    pr[3072] = nih; pr[4096] = nil; pr[5120] = nih;
    __nv_bfloat16* pi = base + (n_re + 1) * GK + e;    // imag-out row
    pi[0] = ih; pi[1024] = il; pi[2048] = ih;
    pi[3072] = rh; pi[4096] = rl; pi[5120] = rh;
}

__global__ __launch_bounds__(256) void pack_B_proj(
    const float* __restrict__ wq_re, const float* __restrict__ wq_im,
    const float* __restrict__ wk_re, const float* __restrict__ wk_im,
    const float* __restrict__ wv_re, const float* __restrict__ wv_im)
{
    int idx = blockIdx.x * 256 + threadIdx.x;          // < 5242880
    int c = idx >> 10, e = idx & 1023;
    const float *wre, *wim; size_t off;
    if (c < 2048)      { wre = wq_re; wim = wq_im; off = (size_t)c * 1024 + e; }
    else if (c < 4096) { wre = wk_re; wim = wk_im; off = (size_t)(c - 2048) * 1024 + e; }
    else               { wre = wv_re; wim = wv_im; off = (size_t)(c - 4096) * 1024 + e; }
    write_B_rows(g_Bproj, (size_t)(2 * c), e, wre[off], wim[off]);
}

__global__ __launch_bounds__(256) void pack_B_out(
    const float* __restrict__ wo_re, const float* __restrict__ wo_im)
{
    int idx = blockIdx.x * 256 + threadIdx.x;          // < 1048576
    int f = idx >> 10, e = idx & 1023;
    write_B_rows(g_Bout, (size_t)(2 * f), e,
                 wo_re[(size_t)e * 1024 + f], wo_im[(size_t)e * 1024 + f]);
}

// ---------------- HMMA bf16 GEMM ---------------------------------------------
// D[4096 x N] = A[4096 x GK] * B[N x GK]^T, CTA tile 128x256, K-chunk 32,
// 4-stage cp.async pipeline. 8 warps in 2(M)x4(N), each 64x64 via m16n8k16.
// smem rows padded to 80B (32 bf16 data = 64B) -> conflict-free ldmatrix.
#define ROWB   80
#define STAGEB (384 * ROWB)          // 30720: A(128 rows) + B(256 rows)
#define BOFF   (128 * ROWB)          // B tile offset within a stage

__device__ __forceinline__ void load_stage(
    uint32_t smb, int stage, const __nv_bfloat16* A, const __nv_bfloat16* B,
    int rowBase, int colBase, int kk, int tid)
{
    uint32_t base = smb + stage * STAGEB;
#pragma unroll
    for (int i = 0; i < 2; ++i) {                    // A: 512 x 16B
        int v = tid + i * 256, row = v >> 2, seg = v & 3;
        cp_async16(base + row * ROWB + seg * 16,
                   A + (size_t)(rowBase + row) * GK + kk + seg * 8);
    }
#pragma unroll
    for (int i = 0; i < 4; ++i) {                    // B: 1024 x 16B
        int v = tid + i * 256, row = v >> 2, seg = v & 3;
        cp_async16(base + BOFF + row * ROWB + seg * 16,
                   B + (size_t)(colBase + row) * GK + kk + seg * 8);
    }
}

__global__ __launch_bounds__(256) void gemm_hmma(
    int mode, float* __restrict__ Dout,
    const float* __restrict__ xre, const float* __restrict__ xim)
{
    extern __shared__ char sm[];
    const uint32_t smb = smem_u32(sm);
    const int tid = threadIdx.x;
    const int wid = tid >> 5, lane = tid & 31;
    const int warpM = wid >> 2, warpN = wid & 3;     // 2 x 4
    const int rowBase = blockIdx.x * 128;
    const int colBase = blockIdx.y * 256;
    const __nv_bfloat16* A = mode ? g_Aatt : g_Aproj;
    const __nv_bfloat16* B = mode ? g_Bout : g_Bproj;

    float acc[4][8][4];
#pragma unroll
    for (int i = 0; i < 4; ++i)
#pragma unroll
        for (int j = 0; j < 8; ++j)
#pragma unroll
            for (int k = 0; k < 4; ++k) acc[i][j][k] = 0.f;

    // prologue: 3 stages in flight
    load_stage(smb, 0, A, B, rowBase, colBase, 0, tid);  CP_COMMIT();
    load_stage(smb, 1, A, B, rowBase, colBase, 32, tid); CP_COMMIT();
    load_stage(smb, 2, A, B, rowBase, colBase, 64, tid); CP_COMMIT();

    const uint32_t aRowAddr = smb + (warpM * 64 + (lane & 15)) * ROWB + (lane >> 4) * 16;
    const uint32_t bRowAddr = smb + BOFF + (warpN * 64 + (lane & 15)) * ROWB + (lane >> 4) * 16;

#pragma unroll 1
    for (int c = 0; c < NCHUNK; ++c) {
        CP_WAIT2();
        __syncthreads();
        const uint32_t stoff = (c & 3) * STAGEB;
#pragma unroll
        for (int s = 0; s < 2; ++s) {
            uint32_t a[4][4], b[8][2];
#pragma unroll
            for (int i = 0; i < 4; ++i)
                ldsm_x4(a[i][0], a[i][1], a[i][2], a[i][3],
                        aRowAddr + stoff + i * 16 * ROWB + s * 32);
#pragma unroll
            for (int jj = 0; jj < 4; ++jj) {
                uint32_t r0, r1, r2, r3;
                ldsm_x4(r0, r1, r2, r3,
                        bRowAddr + stoff + jj * 16 * ROWB + s * 32);
                b[2 * jj][0] = r0; b[2 * jj][1] = r2;
                b[2 * jj + 1][0] = r1; b[2 * jj + 1][1] = r3;
            }
#pragma unroll
            for (int i = 0; i < 4; ++i)
#pragma unroll
                for (int j = 0; j < 8; ++j)
                    mma_bf16(acc[i][j], a[i], b[j]);
        }
        if (c + 3 < NCHUNK)
            load_stage(smb, (c + 3) & 3, A, B, rowBase, colBase, (c + 3) * 32, tid);
        CP_COMMIT();
    }

    // epilogue: lane holds D rows {g, g+8}, complex col pair per (i,j)
    const int lrow = lane >> 2;
#pragma unroll
    for (int i = 0; i < 4; ++i) {
        int r0 = rowBase + warpM * 64 + i * 16 + lrow;
#pragma unroll
        for (int j = 0; j < 8; ++j) {
            int cc = (colBase + warpN * 64 + j * 8 + (lane & 3) * 2) >> 1;
            float2 v0 = make_float2(acc[i][j][0], acc[i][j][1]);   // row r0
            float2 v1 = make_float2(acc[i][j][2], acc[i][j][3]);   // row r0+8
            if (mode == 0) {
#pragma unroll
                for (int t = 0; t < 2; ++t) {
                    int r = r0 + t * 8;
                    int s = r >> 2, bb = r & 3;
                    float2 val = t ? v1 : v0;
                    if (cc < 2048)
                        g_q[(((size_t)bb * 16 + (cc >> 7)) * 1024 + s) * 128 + (cc & 127)] = val;
                    else if (cc < 4096) {
                        int u = cc - 2048;
                        g_k[(((size_t)bb * 16 + (u >> 7)) * 1024 + s) * 128 + (u & 127)] = val;
                    } else {
                        int u = cc - 4096;
                        g_v[(((size_t)bb * 16 + (u >> 6)) * 1024 + s) * 64 + (u & 63)] = val;
                    }
                }
            } else {
                size_t i0 = (size_t)r0 * 1024 + cc;
                size_t i1 = (size_t)(r0 + 8) * 1024 + cc;
                Dout[i0]       = v0.x + xre[i0];
                Dout[SBE + i0] = v0.y + xim[i0];
                Dout[i1]       = v1.x + xre[i1];
                Dout[SBE + i1] = v1.y + xim[i1];
            }
        }
    }
}

// ---------------- attention (R1-proven SIMT flash) ---------------------------
__global__ __launch_bounds__(1024) void attn_kernel()
{
    extern __shared__ char smraw[];
    float2* q_s = (float2*)smraw;
    float2* k_s = q_s + 32 * 128;
    float2* v_s = k_s + 128 * 33;

    const int tile = blockIdx.x;
    const int bh = blockIdx.y;
    const int warp = threadIdx.x >> 5;
    const int lane = threadIdx.x & 31;
    const int srow = tile * 32 + warp;

    const float2* qbase = g_q + ((long)bh * Ssz + tile * 32) * Msz;
    for (int i = threadIdx.x; i < 32 * 128; i += 1024)
        q_s[i] = qbase[i];

    float run_max = -INFINITY;
    float run_sum = 0.f;
    float2 acc0 = make_float2(0.f, 0.f);
    float2 acc1 = make_float2(0.f, 0.f);
    const float inv_sqrt_m = 0.088388347648318447f;

    for (int kt = 0; kt <= tile; ++kt) {
        const float2* kbase = g_k + ((long)bh * Ssz + kt * 32) * Msz;
        for (int i = threadIdx.x; i < 32 * 128; i += 1024) {
            int t = i >> 7, m = i & 127;
            k_s[m * 33 + t] = kbase[i];
        }
        const float2* vbase = g_v + ((long)bh * Ssz + kt * 32) * Vsz;
        for (int i = threadIdx.x; i < 32 * 64; i += 1024)
            v_s[i] = vbase[i];
        __syncthreads();

        float sr = 0.f, si = 0.f;
        const float2* qrow = q_s + warp * 128;
#pragma unroll 8
        for (int m = 0; m < 128; ++m) {
            float2 qv = qrow[m];
            float2 kv = k_s[m * 33 + lane];
            sr = fmaf(qv.x, kv.x, sr);
            sr = fmaf(-qv.y, kv.y, sr);
            si = fmaf(qv.x, kv.y, si);
            si = fmaf(qv.y, kv.x, si);
        }
        int tcol = kt * 32 + lane;
        float amp = (tcol <= srow) ? sqrtf(sr * sr + si * si) * inv_sqrt_m
                                   : -INFINITY;
        float tmax = amp;
#pragma unroll
        for (int o = 16; o > 0; o >>= 1)
            tmax = fmaxf(tmax, __shfl_xor_sync(0xffffffffu, tmax, o));
        float nmax = fmaxf(run_max, tmax);
        float corr = __expf(run_max - nmax);
        float p = __expf(amp - nmax);
        float psum = p;
#pragma unroll
        for (int o = 16; o > 0; o >>= 1)
            psum += __shfl_xor_sync(0xffffffffu, psum, o);
        run_sum = run_sum * corr + psum;
        run_max = nmax;
        acc0.x *= corr; acc0.y *= corr;
        acc1.x *= corr; acc1.y *= corr;

#pragma unroll
        for (int t = 0; t < 32; ++t) {
            float pt = __shfl_sync(0xffffffffu, p, t);
            float2 v0 = v_s[t * 64 + lane];
            float2 v1 = v_s[t * 64 + lane + 32];
            acc0.x = fmaf(pt, v0.x, acc0.x);
            acc0.y = fmaf(pt, v0.y, acc0.y);
            acc1.x = fmaf(pt, v1.x, acc1.x);
            acc1.y = fmaf(pt, v1.y, acc1.y);
        }
        __syncthreads();
    }

    float inv = 1.0f / run_sum;
    int b = bh >> 4;
    int h = bh & 15;
    long base = ((long)srow * Bsz + b) * Esz + h * Vsz;
    g_upd[base + lane]      = make_float2(acc0.x * inv, acc0.y * inv);
    g_upd[base + lane + 32] = make_float2(acc1.x * inv, acc1.y * inv);
}

// ---------------------------------------------------------------------------
extern "C" void kernel_launch(void* const* d_in, const int* in_sizes, int n_in,
                              void* d_out, int out_size)
{
    const float* xre = (const float*)d_in[0];
    const float* xim = (const float*)d_in[1];
    const float* wq_re = (const float*)d_in[2];
    const float* wq_im = (const float*)d_in[3];
    const float* wk_re = (const float*)d_in[4];
    const float* wk_im = (const float*)d_in[5];
    const float* wv_re = (const float*)d_in[6];
    const float* wv_im = (const float*)d_in[7];
    const float* wo_re = (const float*)d_in[8];
    const float* wo_im = (const float*)d_in[9];
    float* out = (float*)d_out;

    const int gemm_smem = 4 * STAGEB;                 // 122880
    const int attn_smem = (32 * 128 + 128 * 33 + 32 * 64) * (int)sizeof(float2);
    static bool attr_set = false;
    if (!attr_set) {
        cudaFuncSetAttribute(gemm_hmma,
                             cudaFuncAttributeMaxDynamicSharedMemorySize, gemm_smem);
        cudaFuncSetAttribute(attn_kernel,
                             cudaFuncAttributeMaxDynamicSharedMemorySize, attn_smem);
        attr_set = true;
    }

    pack_A_proj<<<16384, 256>>>(xre, xim);
    pack_B_proj<<<20480, 256>>>(wq_re, wq_im, wk_re, wk_im, wv_re, wv_im);
    pack_B_out<<<4096, 256>>>(wo_re, wo_im);

    gemm_hmma<<<dim3(32, 40), 256, gemm_smem>>>(0, nullptr, nullptr, nullptr);

    attn_kernel<<<dim3(32, 64), 1024, attn_smem>>>();

    pack_A_att<<<16384, 256>>>();
    gemm_hmma<<<dim3(32, 8), 256, gemm_smem>>>(1, out, xre, xim);
}

// round 5
// speedup vs baseline: 1.3806x; 1.0076x over previous
#include <cuda_runtime.h>
#include <cuda_bf16.h>
#include <cstdint>
#include <math.h>

#define Ssz 1024
#define Bsz 4
#define Esz 1024
#define Hsz 16
#define Msz 128
#define Vsz 64
#define SBE (Ssz * Bsz * Esz)      // 4194304
#define GK  6144                   // packed K = 6 * 1024
#define NCHUNK (GK / 32)           // 192 K-chunks of 32

// ---------------- scratch (static device globals; no allocs) ----------------
__device__ float2 g_q[Bsz * Hsz * Ssz * Msz];
__device__ float2 g_k[Bsz * Hsz * Ssz * Msz];
__device__ float2 g_v[Bsz * Hsz * Ssz * Vsz];
__device__ float2 g_upd[Ssz * Bsz * Esz];
__device__ __align__(16) __nv_bfloat16 g_Aproj[4096 * GK];
__device__ __align__(16) __nv_bfloat16 g_Bproj[10240 * GK];
__device__ __align__(16) __nv_bfloat16 g_Bout [2048 * GK];
__device__ __align__(16) __nv_bfloat16 g_Aatt [4096 * GK];

// ---------------- helpers ----------------------------------------------------
__device__ __forceinline__ uint32_t smem_u32(const void* p) {
    uint32_t a;
    asm("{ .reg .u64 t; cvta.to.shared.u64 t, %1; cvt.u32.u64 %0, t; }"
        : "=r"(a) : "l"(p));
    return a;
}
__device__ __forceinline__ void cp_async16(uint32_t dst, const void* src) {
    asm volatile("cp.async.cg.shared.global [%0], [%1], 16;"
                 :: "r"(dst), "l"(src) : "memory");
}
#define CP_COMMIT() asm volatile("cp.async.commit_group;" ::: "memory")
#define CP_WAIT2()  asm volatile("cp.async.wait_group 2;" ::: "memory")

__device__ __forceinline__ void ldsm_x4(uint32_t& r0, uint32_t& r1,
                                        uint32_t& r2, uint32_t& r3, uint32_t a) {
    asm volatile("ldmatrix.sync.aligned.m8n8.x4.shared.b16 {%0,%1,%2,%3}, [%4];"
                 : "=r"(r0), "=r"(r1), "=r"(r2), "=r"(r3) : "r"(a));
}
__device__ __forceinline__ void mma_bf16(float* d, const uint32_t* a,
                                         const uint32_t* b) {
    asm volatile(
        "mma.sync.aligned.m16n8k16.row.col.f32.bf16.bf16.f32 "
        "{%0,%1,%2,%3}, {%4,%5,%6,%7}, {%8,%9}, {%0,%1,%2,%3};"
        : "+f"(d[0]), "+f"(d[1]), "+f"(d[2]), "+f"(d[3])
        : "r"(a[0]), "r"(a[1]), "r"(a[2]), "r"(a[3]), "r"(b[0]), "r"(b[1]));
}

__device__ __forceinline__ void split_bf16(float x, __nv_bfloat16& h, __nv_bfloat16& l) {
    h = __float2bfloat16(x);
    l = __float2bfloat16(x - __bfloat162float(h));
}

// ---------------- pack kernels ----------------------------------------------
__global__ __launch_bounds__(256) void pack_A_proj(
    const float* __restrict__ xre, const float* __restrict__ xim)
{
    int idx = blockIdx.x * 256 + threadIdx.x;
    int r = idx >> 10, e = idx & 1023;
    __nv_bfloat16 rh, rl, ih, il;
    split_bf16(xre[idx], rh, rl);
    split_bf16(xim[idx], ih, il);
    __nv_bfloat16* p = g_Aproj + (size_t)r * GK + e;
    p[0] = rh; p[1024] = rh; p[2048] = rl;
    p[3072] = ih; p[4096] = ih; p[5120] = il;
}

__global__ __launch_bounds__(256) void pack_A_att()
{
    int idx = blockIdx.x * 256 + threadIdx.x;
    int r = idx >> 10, e = idx & 1023;
    float2 u = g_upd[idx];
    __nv_bfloat16 rh, rl, ih, il;
    split_bf16(u.x, rh, rl);
    split_bf16(u.y, ih, il);
    __nv_bfloat16* p = g_Aatt + (size_t)r * GK + e;
    p[0] = rh; p[1024] = rh; p[2048] = rl;
    p[3072] = ih; p[4096] = ih; p[5120] = il;
}

__device__ __forceinline__ void write_B_rows(__nv_bfloat16* base, size_t n_re,
                                             int e, float wr, float wi)
{
    __nv_bfloat16 rh, rl, ih, il;
    split_bf16(wr, rh, rl);
    split_bf16(wi, ih, il);
    __nv_bfloat16 nih = __float2bfloat16(-__bfloat162float(ih));
    __nv_bfloat16 nil = __float2bfloat16(-__bfloat162float(il));
    __nv_bfloat16* pr = base + n_re * GK + e;          // real-out row
    pr[0] = rh; pr[1024] = rl; pr[2048] = rh;
    pr[3072] = nih; pr[4096] = nil; pr[5120] = nih;
    __nv_bfloat16* pi = base + (n_re + 1) * GK + e;    // imag-out row
    pi[0] = ih; pi[1024] = il; pi[2048] = ih;
    pi[3072] = rh; pi[4096] = rl; pi[5120] = rh;
}

__global__ __launch_bounds__(256) void pack_B_proj(
    const float* __restrict__ wq_re, const float* __restrict__ wq_im,
    const float* __restrict__ wk_re, const float* __restrict__ wk_im,
    const float* __restrict__ wv_re, const float* __restrict__ wv_im)
{
    int idx = blockIdx.x * 256 + threadIdx.x;          // < 5242880
    int c = idx >> 10, e = idx & 1023;
    const float *wre, *wim; size_t off;
    if (c < 2048)      { wre = wq_re; wim = wq_im; off = (size_t)c * 1024 + e; }
    else if (c < 4096) { wre = wk_re; wim = wk_im; off = (size_t)(c - 2048) * 1024 + e; }
    else               { wre = wv_re; wim = wv_im; off = (size_t)(c - 4096) * 1024 + e; }
    write_B_rows(g_Bproj, (size_t)(2 * c), e, wre[off], wim[off]);
}

__global__ __launch_bounds__(256) void pack_B_out(
    const float* __restrict__ wo_re, const float* __restrict__ wo_im)
{
    int idx = blockIdx.x * 256 + threadIdx.x;          // < 1048576
    int f = idx >> 10, e = idx & 1023;
    write_B_rows(g_Bout, (size_t)(2 * f), e,
                 wo_re[(size_t)e * 1024 + f], wo_im[(size_t)e * 1024 + f]);
}

// ---------------- HMMA bf16 GEMM ---------------------------------------------
// D[4096 x N] = A[4096 x GK] * B[N x GK]^T, CTA tile 128x256, K-chunk 32,
// 4-stage cp.async pipeline. 8 warps in 2(M)x4(N), each 64x64 via m16n8k16.
// smem rows padded to 80B (32 bf16 data = 64B) -> conflict-free ldmatrix.
#define ROWB   80
#define STAGEB (384 * ROWB)          // 30720: A(128 rows) + B(256 rows)
#define BOFF   (128 * ROWB)          // B tile offset within a stage

__device__ __forceinline__ void load_stage(
    uint32_t smb, int stage, const __nv_bfloat16* A, const __nv_bfloat16* B,
    int rowBase, int colBase, int kk, int tid)
{
    uint32_t base = smb + stage * STAGEB;
#pragma unroll
    for (int i = 0; i < 2; ++i) {                    // A: 512 x 16B
        int v = tid + i * 256, row = v >> 2, seg = v & 3;
        cp_async16(base + row * ROWB + seg * 16,
                   A + (size_t)(rowBase + row) * GK + kk + seg * 8);
    }
#pragma unroll
    for (int i = 0; i < 4; ++i) {                    // B: 1024 x 16B
        int v = tid + i * 256, row = v >> 2, seg = v & 3;
        cp_async16(base + BOFF + row * ROWB + seg * 16,
                   B + (size_t)(colBase + row) * GK + kk + seg * 8);
    }
}

__global__ __launch_bounds__(256) void gemm_hmma(
    int mode, float* __restrict__ Dout,
    const float* __restrict__ xre, const float* __restrict__ xim)
{
    extern __shared__ char sm[];
    const uint32_t smb = smem_u32(sm);
    const int tid = threadIdx.x;
    const int wid = tid >> 5, lane = tid & 31;
    const int warpM = wid >> 2, warpN = wid & 3;     // 2 x 4
    const int rowBase = blockIdx.x * 128;
    const int colBase = blockIdx.y * 256;
    const __nv_bfloat16* A = mode ? g_Aatt : g_Aproj;
    const __nv_bfloat16* B = mode ? g_Bout : g_Bproj;

    float acc[4][8][4];
#pragma unroll
    for (int i = 0; i < 4; ++i)
#pragma unroll
        for (int j = 0; j < 8; ++j)
#pragma unroll
            for (int k = 0; k < 4; ++k) acc[i][j][k] = 0.f;

    // prologue: 3 stages in flight
    load_stage(smb, 0, A, B, rowBase, colBase, 0, tid);  CP_COMMIT();
    load_stage(smb, 1, A, B, rowBase, colBase, 32, tid); CP_COMMIT();
    load_stage(smb, 2, A, B, rowBase, colBase, 64, tid); CP_COMMIT();

    const uint32_t aRowAddr = smb + (warpM * 64 + (lane & 15)) * ROWB + (lane >> 4) * 16;
    const uint32_t bRowAddr = smb + BOFF + (warpN * 64 + (lane & 15)) * ROWB + (lane >> 4) * 16;

#pragma unroll 1
    for (int c = 0; c < NCHUNK; ++c) {
        CP_WAIT2();
        __syncthreads();
        const uint32_t stoff = (c & 3) * STAGEB;
#pragma unroll
        for (int s = 0; s < 2; ++s) {
            uint32_t a[4][4], b[8][2];
#pragma unroll
            for (int i = 0; i < 4; ++i)
                ldsm_x4(a[i][0], a[i][1], a[i][2], a[i][3],
                        aRowAddr + stoff + i * 16 * ROWB + s * 32);
#pragma unroll
            for (int jj = 0; jj < 4; ++jj) {
                uint32_t r0, r1, r2, r3;
                ldsm_x4(r0, r1, r2, r3,
                        bRowAddr + stoff + jj * 16 * ROWB + s * 32);
                b[2 * jj][0] = r0; b[2 * jj][1] = r2;
                b[2 * jj + 1][0] = r1; b[2 * jj + 1][1] = r3;
            }
#pragma unroll
            for (int i = 0; i < 4; ++i)
#pragma unroll
                for (int j = 0; j < 8; ++j)
                    mma_bf16(acc[i][j], a[i], b[j]);
        }
        if (c + 3 < NCHUNK)
            load_stage(smb, (c + 3) & 3, A, B, rowBase, colBase, (c + 3) * 32, tid);
        CP_COMMIT();
    }

    // epilogue: lane holds D rows {g, g+8}, complex col pair per (i,j)
    const int lrow = lane >> 2;
#pragma unroll
    for (int i = 0; i < 4; ++i) {
        int r0 = rowBase + warpM * 64 + i * 16 + lrow;
#pragma unroll
        for (int j = 0; j < 8; ++j) {
            int cc = (colBase + warpN * 64 + j * 8 + (lane & 3) * 2) >> 1;
            float2 v0 = make_float2(acc[i][j][0], acc[i][j][1]);   // row r0
            float2 v1 = make_float2(acc[i][j][2], acc[i][j][3]);   // row r0+8
            if (mode == 0) {
#pragma unroll
                for (int t = 0; t < 2; ++t) {
                    int r = r0 + t * 8;
                    int s = r >> 2, bb = r & 3;
                    float2 val = t ? v1 : v0;
                    if (cc < 2048)
                        g_q[(((size_t)bb * 16 + (cc >> 7)) * 1024 + s) * 128 + (cc & 127)] = val;
                    else if (cc < 4096) {
                        int u = cc - 2048;
                        g_k[(((size_t)bb * 16 + (u >> 7)) * 1024 + s) * 128 + (u & 127)] = val;
                    } else {
                        int u = cc - 4096;
                        g_v[(((size_t)bb * 16 + (u >> 6)) * 1024 + s) * 64 + (u & 63)] = val;
                    }
                }
            } else {
                size_t i0 = (size_t)r0 * 1024 + cc;
                size_t i1 = (size_t)(r0 + 8) * 1024 + cc;
                Dout[i0]       = v0.x + xre[i0];
                Dout[SBE + i0] = v0.y + xim[i0];
                Dout[i1]       = v1.x + xre[i1];
                Dout[SBE + i1] = v1.y + xim[i1];
            }
        }
    }
}

// ---------------- attention (R1-proven SIMT flash) ---------------------------
__global__ __launch_bounds__(1024) void attn_kernel()
{
    extern __shared__ char smraw[];
    float2* q_s = (float2*)smraw;
    float2* k_s = q_s + 32 * 128;
    float2* v_s = k_s + 128 * 33;

    const int tile = blockIdx.x;
    const int bh = blockIdx.y;
    const int warp = threadIdx.x >> 5;
    const int lane = threadIdx.x & 31;
    const int srow = tile * 32 + warp;

    const float2* qbase = g_q + ((long)bh * Ssz + tile * 32) * Msz;
    for (int i = threadIdx.x; i < 32 * 128; i += 1024)
        q_s[i] = qbase[i];

    float run_max = -INFINITY;
    float run_sum = 0.f;
    float2 acc0 = make_float2(0.f, 0.f);
    float2 acc1 = make_float2(0.f, 0.f);
    const float inv_sqrt_m = 0.088388347648318447f;

    for (int kt = 0; kt <= tile; ++kt) {
        const float2* kbase = g_k + ((long)bh * Ssz + kt * 32) * Msz;
        for (int i = threadIdx.x; i < 32 * 128; i += 1024) {
            int t = i >> 7, m = i & 127;
            k_s[m * 33 + t] = kbase[i];
        }
        const float2* vbase = g_v + ((long)bh * Ssz + kt * 32) * Vsz;
        for (int i = threadIdx.x; i < 32 * 64; i += 1024)
            v_s[i] = vbase[i];
        __syncthreads();

        float sr = 0.f, si = 0.f;
        const float2* qrow = q_s + warp * 128;
#pragma unroll 8
        for (int m = 0; m < 128; ++m) {
            float2 qv = qrow[m];
            float2 kv = k_s[m * 33 + lane];
            sr = fmaf(qv.x, kv.x, sr);
            sr = fmaf(-qv.y, kv.y, sr);
            si = fmaf(qv.x, kv.y, si);
            si = fmaf(qv.y, kv.x, si);
        }
        int tcol = kt * 32 + lane;
        float amp = (tcol <= srow) ? sqrtf(sr * sr + si * si) * inv_sqrt_m
                                   : -INFINITY;
        float tmax = amp;
#pragma unroll
        for (int o = 16; o > 0; o >>= 1)
            tmax = fmaxf(tmax, __shfl_xor_sync(0xffffffffu, tmax, o));
        float nmax = fmaxf(run_max, tmax);
        float corr = __expf(run_max - nmax);
        float p = __expf(amp - nmax);
        float psum = p;
#pragma unroll
        for (int o = 16; o > 0; o >>= 1)
            psum += __shfl_xor_sync(0xffffffffu, psum, o);
        run_sum = run_sum * corr + psum;
        run_max = nmax;
        acc0.x *= corr; acc0.y *= corr;
        acc1.x *= corr; acc1.y *= corr;

#pragma unroll
        for (int t = 0; t < 32; ++t) {
            float pt = __shfl_sync(0xffffffffu, p, t);
            float2 v0 = v_s[t * 64 + lane];
            float2 v1 = v_s[t * 64 + lane + 32];
            acc0.x = fmaf(pt, v0.x, acc0.x);
            acc0.y = fmaf(pt, v0.y, acc0.y);
            acc1.x = fmaf(pt, v1.x, acc1.x);
            acc1.y = fmaf(pt, v1.y, acc1.y);
        }
        __syncthreads();
    }

    float inv = 1.0f / run_sum;
    int b = bh >> 4;
    int h = bh & 15;
    long base = ((long)srow * Bsz + b) * Esz + h * Vsz;
    g_upd[base + lane]      = make_float2(acc0.x * inv, acc0.y * inv);
    g_upd[base + lane + 32] = make_float2(acc1.x * inv, acc1.y * inv);
}

// ---------------------------------------------------------------------------
extern "C" void kernel_launch(void* const* d_in, const int* in_sizes, int n_in,
                              void* d_out, int out_size)
{
    const float* xre = (const float*)d_in[0];
    const float* xim = (const float*)d_in[1];
    const float* wq_re = (const float*)d_in[2];
    const float* wq_im = (const float*)d_in[3];
    const float* wk_re = (const float*)d_in[4];
    const float* wk_im = (const float*)d_in[5];
    const float* wv_re = (const float*)d_in[6];
    const float* wv_im = (const float*)d_in[7];
    const float* wo_re = (const float*)d_in[8];
    const float* wo_im = (const float*)d_in[9];
    float* out = (float*)d_out;

    const int gemm_smem = 4 * STAGEB;                 // 122880
    const int attn_smem = (32 * 128 + 128 * 33 + 32 * 64) * (int)sizeof(float2);
    static bool attr_set = false;
    if (!attr_set) {
        cudaFuncSetAttribute(gemm_hmma,
                             cudaFuncAttributeMaxDynamicSharedMemorySize, gemm_smem);
        cudaFuncSetAttribute(attn_kernel,
                             cudaFuncAttributeMaxDynamicSharedMemorySize, attn_smem);
        attr_set = true;
    }

    pack_A_proj<<<16384, 256>>>(xre, xim);
    pack_B_proj<<<20480, 256>>>(wq_re, wq_im, wk_re, wk_im, wv_re, wv_im);
    pack_B_out<<<4096, 256>>>(wo_re, wo_im);

    gemm_hmma<<<dim3(32, 40), 256, gemm_smem>>>(0, nullptr, nullptr, nullptr);

    attn_kernel<<<dim3(32, 64), 1024, attn_smem>>>();

    pack_A_att<<<16384, 256>>>();
    gemm_hmma<<<dim3(32, 8), 256, gemm_smem>>>(1, out, xre, xim);
}

// round 6
// speedup vs baseline: 2.1182x; 1.5342x over previous
#include <cuda_runtime.h>
#include <cuda_bf16.h>
#include <cstdint>
#include <math.h>

#define Ssz 1024
#define Bsz 4
#define Esz 1024
#define SBE (Ssz * Bsz * Esz)
#define GK  6144
#define NCHUNK (GK / 32)

// ---------------- scratch -----------------------------------------------------
__device__ __align__(16) __nv_bfloat16 g_Aproj[4096 * GK];
__device__ __align__(16) __nv_bfloat16 g_Bproj[10240 * GK];
__device__ __align__(16) __nv_bfloat16 g_Bout [2048 * GK];
__device__ __align__(16) __nv_bfloat16 g_Aatt [4096 * GK];
__device__ __align__(16) __nv_bfloat16 g_qp[64u * 1024 * 512]; // [bh][s][qr_h|qr_l|qi_h|qi_l]
__device__ __align__(16) __nv_bfloat16 g_kp[64u * 1024 * 512];
__device__ __align__(16) __nv_bfloat16 g_vt[64u * 256 * 1024]; // [bh][vc planes][t]

// ---------------- helpers ------------------------------------------------------
__device__ __forceinline__ uint32_t smem_u32(const void* p) {
    uint32_t a;
    asm("{ .reg .u64 t; cvta.to.shared.u64 t, %1; cvt.u32.u64 %0, t; }" : "=r"(a) : "l"(p));
    return a;
}
__device__ __forceinline__ void cp_async16(uint32_t dst, const void* src) {
    asm volatile("cp.async.cg.shared.global [%0], [%1], 16;" :: "r"(dst), "l"(src) : "memory");
}
#define CP_COMMIT() asm volatile("cp.async.commit_group;" ::: "memory")
#define CP_WAIT0()  asm volatile("cp.async.wait_group 0;" ::: "memory")
#define CP_WAIT1()  asm volatile("cp.async.wait_group 1;" ::: "memory")
#define CP_WAIT2()  asm volatile("cp.async.wait_group 2;" ::: "memory")

__device__ __forceinline__ void ldsm_x4(uint32_t& r0, uint32_t& r1,
                                        uint32_t& r2, uint32_t& r3, uint32_t a) {
    asm volatile("ldmatrix.sync.aligned.m8n8.x4.shared.b16 {%0,%1,%2,%3}, [%4];"
                 : "=r"(r0), "=r"(r1), "=r"(r2), "=r"(r3) : "r"(a));
}
__device__ __forceinline__ void mma_bf16(float* d, const uint32_t* a,
                                         uint32_t b0, uint32_t b1) {
    asm volatile(
        "mma.sync.aligned.m16n8k16.row.col.f32.bf16.bf16.f32 "
        "{%0,%1,%2,%3}, {%4,%5,%6,%7}, {%8,%9}, {%0,%1,%2,%3};"
        : "+f"(d[0]), "+f"(d[1]), "+f"(d[2]), "+f"(d[3])
        : "r"(a[0]), "r"(a[1]), "r"(a[2]), "r"(a[3]), "r"(b0), "r"(b1));
}
__device__ __forceinline__ void split_bf16(float x, __nv_bfloat16& h, __nv_bfloat16& l) {
    h = __float2bfloat16(x);
    l = __float2bfloat16(x - __bfloat162float(h));
}
__device__ __forceinline__ uint32_t pack_bf2(float lo, float hi) {
    uint32_t r;
    asm("cvt.rn.bf16x2.f32 %0, %1, %2;" : "=r"(r) : "f"(hi), "f"(lo));
    return r;
}

// ---------------- pack kernels --------------------------------------------------
__global__ __launch_bounds__(256) void pack_A_proj(
    const float* __restrict__ xre, const float* __restrict__ xim)
{
    int idx = blockIdx.x * 256 + threadIdx.x;
    int r = idx >> 10, e = idx & 1023;
    __nv_bfloat16 rh, rl, ih, il;
    split_bf16(xre[idx], rh, rl);
    split_bf16(xim[idx], ih, il);
    __nv_bfloat16* p = g_Aproj + (size_t)r * GK + e;
    p[0] = rh; p[1024] = rh; p[2048] = rl;
    p[3072] = ih; p[4096] = ih; p[5120] = il;
}

__device__ __forceinline__ void write_B_rows(__nv_bfloat16* base, size_t n_re,
                                             int e, float wr, float wi)
{
    __nv_bfloat16 rh, rl, ih, il;
    split_bf16(wr, rh, rl);
    split_bf16(wi, ih, il);
    __nv_bfloat16 nih = __float2bfloat16(-__bfloat162float(ih));
    __nv_bfloat16 nil = __float2bfloat16(-__bfloat162float(il));
    __nv_bfloat16* pr = base + n_re * GK + e;
    pr[0] = rh; pr[1024] = rl; pr[2048] = rh;
    pr[3072] = nih; pr[4096] = nil; pr[5120] = nih;
    __nv_bfloat16* pi = base + (n_re + 1) * GK + e;
    pi[0] = ih; pi[1024] = il; pi[2048] = ih;
    pi[3072] = rh; pi[4096] = rl; pi[5120] = rh;
}

__global__ __launch_bounds__(256) void pack_B_proj(
    const float* __restrict__ wq_re, const float* __restrict__ wq_im,
    const float* __restrict__ wk_re, const float* __restrict__ wk_im,
    const float* __restrict__ wv_re, const float* __restrict__ wv_im)
{
    int idx = blockIdx.x * 256 + threadIdx.x;
    int c = idx >> 10, e = idx & 1023;
    const float *wre, *wim; size_t off;
    if (c < 2048)      { wre = wq_re; wim = wq_im; off = (size_t)c * 1024 + e; }
    else if (c < 4096) { wre = wk_re; wim = wk_im; off = (size_t)(c - 2048) * 1024 + e; }
    else               { wre = wv_re; wim = wv_im; off = (size_t)(c - 4096) * 1024 + e; }
    write_B_rows(g_Bproj, (size_t)(2 * c), e, wre[off], wim[off]);
}

__global__ __launch_bounds__(256) void pack_B_out(
    const float* __restrict__ wo_re, const float* __restrict__ wo_im)
{
    int idx = blockIdx.x * 256 + threadIdx.x;
    int f = idx >> 10, e = idx & 1023;
    write_B_rows(g_Bout, (size_t)(2 * f), e,
                 wo_re[(size_t)e * 1024 + f], wo_im[(size_t)e * 1024 + f]);
}

// ---------------- HMMA GEMM (128x256 tile, K-chunk 32, 4 stages) ---------------
#define ROWB   80
#define STAGEB (384 * ROWB)
#define BOFF   (128 * ROWB)

__device__ __forceinline__ void load_stage(
    uint32_t smb, int stage, const __nv_bfloat16* A, const __nv_bfloat16* B,
    int rowBase, int colBase, int kk, int tid)
{
    uint32_t base = smb + stage * STAGEB;
#pragma unroll
    for (int i = 0; i < 2; ++i) {
        int v = tid + i * 256, row = v >> 2, seg = v & 3;
        cp_async16(base + row * ROWB + seg * 16,
                   A + (size_t)(rowBase + row) * GK + kk + seg * 8);
    }
#pragma unroll
    for (int i = 0; i < 4; ++i) {
        int v = tid + i * 256, row = v >> 2, seg = v & 3;
        cp_async16(base + BOFF + row * ROWB + seg * 16,
                   B + (size_t)(colBase + row) * GK + kk + seg * 8);
    }
}

__global__ __launch_bounds__(256) void gemm_hmma(
    int mode, float* __restrict__ Dout,
    const float* __restrict__ xre, const float* __restrict__ xim)
{
    extern __shared__ char sm[];
    const uint32_t smb = smem_u32(sm);
    const int tid = threadIdx.x;
    const int wid = tid >> 5, lane = tid & 31;
    const int warpM = wid >> 2, warpN = wid & 3;
    const int rowBase = blockIdx.x * 128;
    const int colBase = blockIdx.y * 256;
    const __nv_bfloat16* A = mode ? g_Aatt : g_Aproj;
    const __nv_bfloat16* B = mode ? g_Bout : g_Bproj;

    float acc[4][8][4];
#pragma unroll
    for (int i = 0; i < 4; ++i)
#pragma unroll
        for (int j = 0; j < 8; ++j)
#pragma unroll
            for (int k = 0; k < 4; ++k) acc[i][j][k] = 0.f;

    load_stage(smb, 0, A, B, rowBase, colBase, 0, tid);  CP_COMMIT();
    load_stage(smb, 1, A, B, rowBase, colBase, 32, tid); CP_COMMIT();
    load_stage(smb, 2, A, B, rowBase, colBase, 64, tid); CP_COMMIT();

    const uint32_t aRowAddr = smb + (warpM * 64 + (lane & 15)) * ROWB + (lane >> 4) * 16;
    const uint32_t bRowAddr = smb + BOFF + (warpN * 64 + (lane & 15)) * ROWB + (lane >> 4) * 16;

#pragma unroll 1
    for (int c = 0; c < NCHUNK; ++c) {
        CP_WAIT2();
        __syncthreads();
        const uint32_t stoff = (c & 3) * STAGEB;
#pragma unroll
        for (int s = 0; s < 2; ++s) {
            uint32_t a[4][4], b[8][2];
#pragma unroll
            for (int i = 0; i < 4; ++i)
                ldsm_x4(a[i][0], a[i][1], a[i][2], a[i][3],
                        aRowAddr + stoff + i * 16 * ROWB + s * 32);
#pragma unroll
            for (int jj = 0; jj < 4; ++jj) {
                uint32_t r0, r1, r2, r3;
                ldsm_x4(r0, r1, r2, r3, bRowAddr + stoff + jj * 16 * ROWB + s * 32);
                b[2 * jj][0] = r0; b[2 * jj][1] = r2;
                b[2 * jj + 1][0] = r1; b[2 * jj + 1][1] = r3;
            }
#pragma unroll
            for (int i = 0; i < 4; ++i)
#pragma unroll
                for (int j = 0; j < 8; ++j)
                    mma_bf16(acc[i][j], a[i], b[j][0], b[j][1]);
        }
        if (c + 3 < NCHUNK)
            load_stage(smb, (c + 3) & 3, A, B, rowBase, colBase, (c + 3) * 32, tid);
        CP_COMMIT();
    }

    const int lrow = lane >> 2;
#pragma unroll
    for (int i = 0; i < 4; ++i) {
        int r0 = rowBase + warpM * 64 + i * 16 + lrow;
#pragma unroll
        for (int j = 0; j < 8; ++j) {
            int cc = (colBase + warpN * 64 + j * 8 + (lane & 3) * 2) >> 1;
#pragma unroll
            for (int t = 0; t < 2; ++t) {
                int r = r0 + t * 8;
                float vre = acc[i][j][2 * t], vim = acc[i][j][2 * t + 1];
                if (mode == 0) {
                    int s = r >> 2, bb = r & 3;
                    __nv_bfloat16 rh, rl, ih, il;
                    split_bf16(vre, rh, rl);
                    split_bf16(vim, ih, il);
                    if (cc < 2048) {
                        int h = cc >> 7, m = cc & 127;
                        __nv_bfloat16* d = g_qp + ((size_t)(bb * 16 + h) * 1024 + s) * 512;
                        d[m] = rh; d[128 + m] = rl; d[256 + m] = ih; d[384 + m] = il;
                    } else if (cc < 4096) {
                        int u = cc - 2048, h = u >> 7, m = u & 127;
                        __nv_bfloat16* d = g_kp + ((size_t)(bb * 16 + h) * 1024 + s) * 512;
                        d[m] = rh; d[128 + m] = rl; d[256 + m] = ih; d[384 + m] = il;
                    } else {
                        int u = cc - 4096, h = u >> 6, vc = u & 63;
                        __nv_bfloat16* d = g_vt + (size_t)(bb * 16 + h) * 256 * 1024;
                        d[(size_t)vc * 1024 + s]         = rh;
                        d[(size_t)(64 + vc) * 1024 + s]  = rl;
                        d[(size_t)(128 + vc) * 1024 + s] = ih;
                        d[(size_t)(192 + vc) * 1024 + s] = il;
                    }
                } else {
                    size_t i0 = (size_t)r * 1024 + cc;
                    Dout[i0]       = vre + xre[i0];
                    Dout[SBE + i0] = vim + xim[i0];
                }
            }
        }
    }
}

// ---------------- HMMA flash attention ------------------------------------------
// 128 thr / 4 warps; q-tile 64 (16 rows/warp); key tile 32; double-buffered K,V^T.
#define QPITCH 1040
#define VPITCH 80
#define AT_SMK0 (64 * QPITCH)
#define AT_SMK1 (AT_SMK0 + 32 * QPITCH)
#define AT_SMV0 (AT_SMK1 + 32 * QPITCH)
#define AT_SMV1 (AT_SMV0 + 256 * VPITCH)
#define AT_TOT  (AT_SMV1 + 256 * VPITCH)   // 174080

__device__ __forceinline__ void load_kv(uint32_t smb, int buf,
    const __nv_bfloat16* Kg, const __nv_bfloat16* Vg, int kt, int tid)
{
    uint32_t kdst = smb + (buf ? AT_SMK1 : AT_SMK0);
    const __nv_bfloat16* ksrc = Kg + (size_t)kt * 32 * 512;
#pragma unroll
    for (int i = 0; i < 16; ++i) {
        int c = tid + i * 128, row = c >> 6, seg = c & 63;
        cp_async16(kdst + row * QPITCH + seg * 16, ksrc + (size_t)row * 512 + seg * 8);
    }
    uint32_t vdst = smb + (buf ? AT_SMV1 : AT_SMV0);
#pragma unroll
    for (int i = 0; i < 8; ++i) {
        int c = tid + i * 128, vc = c >> 2, seg = c & 3;
        cp_async16(vdst + vc * VPITCH + seg * 16,
                   Vg + (size_t)vc * 1024 + kt * 32 + seg * 8);
    }
}

__global__ __launch_bounds__(128) void attn_mma()
{
    extern __shared__ char sm[];
    const uint32_t smb = smem_u32(sm);
    const int tid = threadIdx.x, lane = tid & 31, wid = tid >> 5;
    const int qt = 15 - blockIdx.x;
    const int bh = blockIdx.y;
    const int qbase = qt * 64;
    const int nkt = 2 * qt + 2;
    const float scale = 0.088388347648318447f;

    const __nv_bfloat16* Qg = g_qp + ((size_t)bh * 1024 + qbase) * 512;
    const __nv_bfloat16* Kg = g_kp + (size_t)bh * 1024 * 512;
    const __nv_bfloat16* Vg = g_vt + (size_t)bh * 256 * 1024;

#pragma unroll
    for (int i = 0; i < 32; ++i) {
        int c = tid + i * 128, row = c >> 6, seg = c & 63;
        cp_async16(smb + row * QPITCH + seg * 16, Qg + (size_t)row * 512 + seg * 8);
    }
    load_kv(smb, 0, Kg, Vg, 0, tid);
    CP_COMMIT();

    float m0 = -1e30f, m1 = -1e30f, l0 = 0.f, l1 = 0.f;
    float accR[8][4], accI[8][4];
#pragma unroll
    for (int j = 0; j < 8; ++j)
#pragma unroll
        for (int k = 0; k < 4; ++k) { accR[j][k] = 0.f; accI[j][k] = 0.f; }

    const int rowg = qbase + wid * 16 + (lane >> 2);
    const uint32_t aBase = smb + (wid * 16 + (lane & 15)) * QPITCH + (lane >> 4) * 16;

#pragma unroll 1
    for (int kt = 0; kt < nkt; ++kt) {
        if (kt + 1 < nkt) { load_kv(smb, (kt + 1) & 1, Kg, Vg, kt + 1, tid); CP_COMMIT(); CP_WAIT1(); }
        else CP_WAIT0();
        __syncthreads();
        const uint32_t kbuf = smb + ((kt & 1) ? AT_SMK1 : AT_SMK0);
        const uint32_t vbuf = smb + ((kt & 1) ? AT_SMV1 : AT_SMV0);

        float S[4][4][4];
#pragma unroll
        for (int c2 = 0; c2 < 4; ++c2)
#pragma unroll
            for (int n = 0; n < 4; ++n)
#pragma unroll
                for (int q = 0; q < 4; ++q) S[c2][n][q] = 0.f;

        // QK^T: chains rr,ii,ri,ir; 3-term split each; m=128 in 8 k-steps
#pragma unroll
        for (int ks = 0; ks < 8; ++ks) {
            uint32_t ahr[4], alr[4], ahi[4], ali[4];
            uint32_t aa = aBase + ks * 32;
            ldsm_x4(ahr[0], ahr[1], ahr[2], ahr[3], aa);
            ldsm_x4(alr[0], alr[1], alr[2], alr[3], aa + 256);
            ldsm_x4(ahi[0], ahi[1], ahi[2], ahi[3], aa + 512);
            ldsm_x4(ali[0], ali[1], ali[2], ali[3], aa + 768);
#pragma unroll
            for (int ntp = 0; ntp < 2; ++ntp) {
                uint32_t ba = kbuf + (ntp * 16 + (lane & 15)) * QPITCH + (lane >> 4) * 16 + ks * 32;
                uint32_t bhr[4], blr[4], bhi[4], bli[4];
                ldsm_x4(bhr[0], bhr[1], bhr[2], bhr[3], ba);
                ldsm_x4(blr[0], blr[1], blr[2], blr[3], ba + 256);
                ldsm_x4(bhi[0], bhi[1], bhi[2], bhi[3], ba + 512);
                ldsm_x4(bli[0], bli[1], bli[2], bli[3], ba + 768);
#pragma unroll
                for (int t2 = 0; t2 < 2; ++t2) {
                    int nt = 2 * ntp + t2;
                    mma_bf16(S[0][nt], ahr, bhr[t2], bhr[t2 + 2]);
                    mma_bf16(S[0][nt], alr, bhr[t2], bhr[t2 + 2]);
                    mma_bf16(S[0][nt], ahr, blr[t2], blr[t2 + 2]);
                    mma_bf16(S[1][nt], ahi, bhi[t2], bhi[t2 + 2]);
                    mma_bf16(S[1][nt], ali, bhi[t2], bhi[t2 + 2]);
                    mma_bf16(S[1][nt], ahi, bli[t2], bli[t2 + 2]);
                    mma_bf16(S[2][nt], ahr, bhi[t2], bhi[t2 + 2]);
                    mma_bf16(S[2][nt], alr, bhi[t2], bhi[t2 + 2]);
                    mma_bf16(S[2][nt], ahr, bli[t2], bli[t2 + 2]);
                    mma_bf16(S[3][nt], ahi, bhr[t2], bhr[t2 + 2]);
                    mma_bf16(S[3][nt], ali, bhr[t2], bhr[t2 + 2]);
                    mma_bf16(S[3][nt], ahi, blr[t2], blr[t2 + 2]);
                }
            }
        }

        // amp + causal + online softmax
        float mx0 = -1e30f, mx1 = -1e30f;
#pragma unroll
        for (int nt = 0; nt < 4; ++nt)
#pragma unroll
            for (int q = 0; q < 4; ++q) {
                float re = S[0][nt][q] - S[1][nt][q];
                float im = S[2][nt][q] + S[3][nt][q];
                float amp = sqrtf(re * re + im * im) * scale;
                int col = kt * 32 + nt * 8 + (lane & 3) * 2 + (q & 1);
                int row = rowg + ((q >> 1) ? 8 : 0);
                float logit = (col <= row) ? amp : -1e30f;
                S[0][nt][q] = logit;
                if (q < 2) mx0 = fmaxf(mx0, logit);
                else       mx1 = fmaxf(mx1, logit);
            }
        mx0 = fmaxf(mx0, __shfl_xor_sync(~0u, mx0, 1));
        mx0 = fmaxf(mx0, __shfl_xor_sync(~0u, mx0, 2));
        mx1 = fmaxf(mx1, __shfl_xor_sync(~0u, mx1, 1));
        mx1 = fmaxf(mx1, __shfl_xor_sync(~0u, mx1, 2));
        float m0n = fmaxf(m0, mx0), m1n = fmaxf(m1, mx1);
        float corr0 = __expf(m0 - m0n), corr1 = __expf(m1 - m1n);
        float ph[4][4], pl[4][4];
        float sum0 = 0.f, sum1 = 0.f;
#pragma unroll
        for (int nt = 0; nt < 4; ++nt)
#pragma unroll
            for (int q = 0; q < 4; ++q) {
                float p = __expf(S[0][nt][q] - ((q < 2) ? m0n : m1n));
                if (q < 2) sum0 += p; else sum1 += p;
                float h = __bfloat162float(__float2bfloat16(p));
                ph[nt][q] = h;
                pl[nt][q] = p - h;
            }
        sum0 += __shfl_xor_sync(~0u, sum0, 1);
        sum0 += __shfl_xor_sync(~0u, sum0, 2);
        sum1 += __shfl_xor_sync(~0u, sum1, 1);
        sum1 += __shfl_xor_sync(~0u, sum1, 2);
        l0 = l0 * corr0 + sum0;
        l1 = l1 * corr1 + sum1;
        m0 = m0n; m1 = m1n;
#pragma unroll
        for (int j = 0; j < 8; ++j) {
            accR[j][0] *= corr0; accR[j][1] *= corr0;
            accR[j][2] *= corr1; accR[j][3] *= corr1;
            accI[j][0] *= corr0; accI[j][1] *= corr0;
            accI[j][2] *= corr1; accI[j][3] *= corr1;
        }

        // P*V (3-term split), V^T in smem: rows vr_h|vr_l|vi_h|vi_l
#pragma unroll
        for (int s = 0; s < 2; ++s) {
            uint32_t Ah[4], Al[4];
            Ah[0] = pack_bf2(ph[2 * s][0], ph[2 * s][1]);
            Ah[1] = pack_bf2(ph[2 * s][2], ph[2 * s][3]);
            Ah[2] = pack_bf2(ph[2 * s + 1][0], ph[2 * s + 1][1]);
            Ah[3] = pack_bf2(ph[2 * s + 1][2], ph[2 * s + 1][3]);
            Al[0] = pack_bf2(pl[2 * s][0], pl[2 * s][1]);
            Al[1] = pack_bf2(pl[2 * s][2], pl[2 * s][3]);
            Al[2] = pack_bf2(pl[2 * s + 1][0], pl[2 * s + 1][1]);
            Al[3] = pack_bf2(pl[2 * s + 1][2], pl[2 * s + 1][3]);
#pragma unroll
            for (int pr = 0; pr < 4; ++pr) {
                uint32_t va = vbuf + (pr * 16 + (lane & 15)) * VPITCH + (lane >> 4) * 16 + s * 32;
                uint32_t vh[4], vl[4];
                ldsm_x4(vh[0], vh[1], vh[2], vh[3], va);
                ldsm_x4(vl[0], vl[1], vl[2], vl[3], va + 64 * VPITCH);
                mma_bf16(accR[2 * pr],     Ah, vh[0], vh[2]);
                mma_bf16(accR[2 * pr],     Al, vh[0], vh[2]);
                mma_bf16(accR[2 * pr],     Ah, vl[0], vl[2]);
                mma_bf16(accR[2 * pr + 1], Ah, vh[1], vh[3]);
                mma_bf16(accR[2 * pr + 1], Al, vh[1], vh[3]);
                mma_bf16(accR[2 * pr + 1], Ah, vl[1], vl[3]);
                ldsm_x4(vh[0], vh[1], vh[2], vh[3], va + 128 * VPITCH);
                ldsm_x4(vl[0], vl[1], vl[2], vl[3], va + 192 * VPITCH);
                mma_bf16(accI[2 * pr],     Ah, vh[0], vh[2]);
                mma_bf16(accI[2 * pr],     Al, vh[0], vh[2]);
                mma_bf16(accI[2 * pr],     Ah, vl[0], vl[2]);
                mma_bf16(accI[2 * pr + 1], Ah, vh[1], vh[3]);
                mma_bf16(accI[2 * pr + 1], Al, vh[1], vh[3]);
                mma_bf16(accI[2 * pr + 1], Ah, vl[1], vl[3]);
            }
        }
        __syncthreads();
    }

    // epilogue: normalize + write packed split-bf16 rows for out-GEMM
    const float inv0 = 1.0f / l0, inv1 = 1.0f / l1;
    const int b = bh >> 4, h = bh & 15;
#pragma unroll
    for (int t = 0; t < 2; ++t) {
        int srow = rowg + t * 8;
        size_t r = (size_t)srow * 4 + b;
        float inv = t ? inv1 : inv0;
#pragma unroll
        for (int j = 0; j < 8; ++j)
#pragma unroll
            for (int e2 = 0; e2 < 2; ++e2) {
                int vc = j * 8 + (lane & 3) * 2 + e2;
                float re = accR[j][2 * t + e2] * inv;
                float im = accI[j][2 * t + e2] * inv;
                __nv_bfloat16 rh, rl, ih, il;
                split_bf16(re, rh, rl);
                split_bf16(im, ih, il);
                __nv_bfloat16* p = g_Aatt + r * GK + (h * 64 + vc);
                p[0] = rh; p[1024] = rh; p[2048] = rl;
                p[3072] = ih; p[4096] = ih; p[5120] = il;
            }
    }
}

// ---------------------------------------------------------------------------
extern "C" void kernel_launch(void* const* d_in, const int* in_sizes, int n_in,
                              void* d_out, int out_size)
{
    const float* xre = (const float*)d_in[0];
    const float* xim = (const float*)d_in[1];
    float* out = (float*)d_out;

    const int gemm_smem = 4 * STAGEB;
    static bool attr_set = false;
    if (!attr_set) {
        cudaFuncSetAttribute(gemm_hmma,
                             cudaFuncAttributeMaxDynamicSharedMemorySize, gemm_smem);
        cudaFuncSetAttribute(attn_mma,
                             cudaFuncAttributeMaxDynamicSharedMemorySize, AT_TOT);
        attr_set = true;
    }

    pack_A_proj<<<16384, 256>>>(xre, xim);
    pack_B_proj<<<20480, 256>>>((const float*)d_in[2], (const float*)d_in[3],
                                (const float*)d_in[4], (const float*)d_in[5],
                                (const float*)d_in[6], (const float*)d_in[7]);
    pack_B_out<<<4096, 256>>>((const float*)d_in[8], (const float*)d_in[9]);

    gemm_hmma<<<dim3(32, 40), 256, gemm_smem>>>(0, nullptr, nullptr, nullptr);

    attn_mma<<<dim3(16, 64), 128, AT_TOT>>>();

    gemm_hmma<<<dim3(32, 8), 256, gemm_smem>>>(1, out, xre, xim);
}

// round 7
// speedup vs baseline: 3.1458x; 1.4851x over previous
#include <cuda_runtime.h>
#include <cuda_fp16.h>
#include <cstdint>
#include <math.h>

#define Ssz 1024
#define Bsz 4
#define Esz 1024
#define SBE (Ssz * Bsz * Esz)
#define GK  4096                    // 4 planes x 1024 (fp16 2-term split)
#define NCHUNK (GK / 32)            // 128

// ---------------- scratch -----------------------------------------------------
__device__ __align__(16) __half g_Aproj[4096u * GK];
__device__ __align__(16) __half g_Bproj[10240u * GK];
__device__ __align__(16) __half g_Bout [2048u * GK];
__device__ __align__(16) __half g_Aatt [4096u * GK];
__device__ __align__(16) __half g_qp[64u * 1024 * 512]; // [bh][s][qr_h|qr_l|qi_h|qi_l]
__device__ __align__(16) __half g_kp[64u * 1024 * 256]; // [bh][t][kr_h|ki_h]
__device__ __align__(16) __half g_vt[64u * 128 * 1024]; // [bh][vr(64)|vi(64) planes][t]

// ---------------- helpers ------------------------------------------------------
__device__ __forceinline__ uint32_t smem_u32(const void* p) {
    uint32_t a;
    asm("{ .reg .u64 t; cvta.to.shared.u64 t, %1; cvt.u32.u64 %0, t; }" : "=r"(a) : "l"(p));
    return a;
}
__device__ __forceinline__ void cp_async16(uint32_t dst, const void* src) {
    asm volatile("cp.async.cg.shared.global [%0], [%1], 16;" :: "r"(dst), "l"(src) : "memory");
}
#define CP_COMMIT() asm volatile("cp.async.commit_group;" ::: "memory")
#define CP_WAIT0()  asm volatile("cp.async.wait_group 0;" ::: "memory")
#define CP_WAIT1()  asm volatile("cp.async.wait_group 1;" ::: "memory")
#define CP_WAIT2()  asm volatile("cp.async.wait_group 2;" ::: "memory")

__device__ __forceinline__ void ldsm_x4(uint32_t& r0, uint32_t& r1,
                                        uint32_t& r2, uint32_t& r3, uint32_t a) {
    asm volatile("ldmatrix.sync.aligned.m8n8.x4.shared.b16 {%0,%1,%2,%3}, [%4];"
                 : "=r"(r0), "=r"(r1), "=r"(r2), "=r"(r3) : "r"(a));
}
__device__ __forceinline__ void mma_f16(float* d, const uint32_t* a,
                                        uint32_t b0, uint32_t b1) {
    asm volatile(
        "mma.sync.aligned.m16n8k16.row.col.f32.f16.f16.f32 "
        "{%0,%1,%2,%3}, {%4,%5,%6,%7}, {%8,%9}, {%0,%1,%2,%3};"
        : "+f"(d[0]), "+f"(d[1]), "+f"(d[2]), "+f"(d[3])
        : "r"(a[0]), "r"(a[1]), "r"(a[2]), "r"(a[3]), "r"(b0), "r"(b1));
}
__device__ __forceinline__ void split_fp16(float x, __half& h, __half& l) {
    h = __float2half(x);
    l = __float2half(x - __half2float(h));
}
__device__ __forceinline__ uint32_t pack_h2(float lo, float hi) {
    uint32_t r;
    asm("cvt.rn.f16x2.f32 %0, %1, %2;" : "=r"(r) : "f"(hi), "f"(lo));
    return r;
}
// e^x for x <= ~0, FMA-pipe only (no MUFU)
__device__ __forceinline__ float fexp(float x) {
    float t = fmaxf(x * 1.4426950408889634f, -126.0f);
    int k = __float2int_rn(t);
    float f = (t - (float)k) * 0.6931471805599453f;
    float p = 1.0f + f * (1.0f + f * (0.5f + f * (0.16666667f +
                   f * (0.041666667f + f * 0.0083333333f))));
    return p * __int_as_float((k + 127) << 23);
}
// sqrt(re^2+im^2) via bit-hack rsqrt + 2 Newton iters (no MUFU)
__device__ __forceinline__ float famp(float re, float im) {
    float z = fmaf(re, re, im * im);
    z = fmaxf(z, 1e-37f);
    float r = __int_as_float(0x5f3759df - (__float_as_int(z) >> 1));
    r = r * fmaf(-0.5f * z * r, r, 1.5f);
    r = r * fmaf(-0.5f * z * r, r, 1.5f);
    return z * r;
}

// ---------------- pack kernels --------------------------------------------------
__global__ __launch_bounds__(256) void pack_A_proj(
    const float* __restrict__ xre, const float* __restrict__ xim)
{
    int idx = blockIdx.x * 256 + threadIdx.x;
    int r = idx >> 10, e = idx & 1023;
    __half rh, rl, ih, il;
    split_fp16(xre[idx], rh, rl);
    split_fp16(xim[idx], ih, il);
    __half* p = g_Aproj + (size_t)r * GK + e;
    p[0] = rh; p[1024] = rl; p[2048] = ih; p[3072] = il;
}

// B rows: real out = [wrh, wrh, -wih, -wih]; imag out = [wih, wih, wrh, wrh]
__device__ __forceinline__ void write_B_rows(__half* base, size_t n_re,
                                             int e, float wr, float wi)
{
    __half rh = __float2half(wr);
    __half ih = __float2half(wi);
    __half nih = __hneg(ih);
    __half* pr = base + n_re * GK + e;
    pr[0] = rh; pr[1024] = rh; pr[2048] = nih; pr[3072] = nih;
    __half* pi = base + (n_re + 1) * GK + e;
    pi[0] = ih; pi[1024] = ih; pi[2048] = rh; pi[3072] = rh;
}

__global__ __launch_bounds__(256) void pack_B_proj(
    const float* __restrict__ wq_re, const float* __restrict__ wq_im,
    const float* __restrict__ wk_re, const float* __restrict__ wk_im,
    const float* __restrict__ wv_re, const float* __restrict__ wv_im)
{
    int idx = blockIdx.x * 256 + threadIdx.x;
    int c = idx >> 10, e = idx & 1023;
    const float *wre, *wim; size_t off;
    if (c < 2048)      { wre = wq_re; wim = wq_im; off = (size_t)c * 1024 + e; }
    else if (c < 4096) { wre = wk_re; wim = wk_im; off = (size_t)(c - 2048) * 1024 + e; }
    else               { wre = wv_re; wim = wv_im; off = (size_t)(c - 4096) * 1024 + e; }
    write_B_rows(g_Bproj, (size_t)(2 * c), e, wre[off], wim[off]);
}

__global__ __launch_bounds__(256) void pack_B_out(
    const float* __restrict__ wo_re, const float* __restrict__ wo_im)
{
    int idx = blockIdx.x * 256 + threadIdx.x;
    int f = idx >> 10, e = idx & 1023;
    write_B_rows(g_Bout, (size_t)(2 * f), e,
                 wo_re[(size_t)e * 1024 + f], wo_im[(size_t)e * 1024 + f]);
}

// ---------------- HMMA GEMM (128x256 tile, K-chunk 32, 4 stages) ---------------
#define ROWB   80
#define STAGEB (384 * ROWB)
#define BOFF   (128 * ROWB)

__device__ __forceinline__ void load_stage(
    uint32_t smb, int stage, const __half* A, const __half* B,
    int rowBase, int colBase, int kk, int tid)
{
    uint32_t base = smb + stage * STAGEB;
#pragma unroll
    for (int i = 0; i < 2; ++i) {
        int v = tid + i * 256, row = v >> 2, seg = v & 3;
        cp_async16(base + row * ROWB + seg * 16,
                   A + (size_t)(rowBase + row) * GK + kk + seg * 8);
    }
#pragma unroll
    for (int i = 0; i < 4; ++i) {
        int v = tid + i * 256, row = v >> 2, seg = v & 3;
        cp_async16(base + BOFF + row * ROWB + seg * 16,
                   B + (size_t)(colBase + row) * GK + kk + seg * 8);
    }
}

__global__ __launch_bounds__(256) void gemm_hmma(
    int mode, float* __restrict__ Dout,
    const float* __restrict__ xre, const float* __restrict__ xim)
{
    extern __shared__ char sm[];
    const uint32_t smb = smem_u32(sm);
    const int tid = threadIdx.x;
    const int wid = tid >> 5, lane = tid & 31;
    const int warpM = wid >> 2, warpN = wid & 3;
    const int rowBase = blockIdx.x * 128;
    const int colBase = blockIdx.y * 256;
    const __half* A = mode ? g_Aatt : g_Aproj;
    const __half* B = mode ? g_Bout : g_Bproj;

    float acc[4][8][4];
#pragma unroll
    for (int i = 0; i < 4; ++i)
#pragma unroll
        for (int j = 0; j < 8; ++j)
#pragma unroll
            for (int k = 0; k < 4; ++k) acc[i][j][k] = 0.f;

    load_stage(smb, 0, A, B, rowBase, colBase, 0, tid);  CP_COMMIT();
    load_stage(smb, 1, A, B, rowBase, colBase, 32, tid); CP_COMMIT();
    load_stage(smb, 2, A, B, rowBase, colBase, 64, tid); CP_COMMIT();

    const uint32_t aRowAddr = smb + (warpM * 64 + (lane & 15)) * ROWB + (lane >> 4) * 16;
    const uint32_t bRowAddr = smb + BOFF + (warpN * 64 + (lane & 15)) * ROWB + (lane >> 4) * 16;

#pragma unroll 1
    for (int c = 0; c < NCHUNK; ++c) {
        CP_WAIT2();
        __syncthreads();
        const uint32_t stoff = (c & 3) * STAGEB;
#pragma unroll
        for (int s = 0; s < 2; ++s) {
            uint32_t a[4][4], b[8][2];
#pragma unroll
            for (int i = 0; i < 4; ++i)
                ldsm_x4(a[i][0], a[i][1], a[i][2], a[i][3],
                        aRowAddr + stoff + i * 16 * ROWB + s * 32);
#pragma unroll
            for (int jj = 0; jj < 4; ++jj) {
                uint32_t r0, r1, r2, r3;
                ldsm_x4(r0, r1, r2, r3, bRowAddr + stoff + jj * 16 * ROWB + s * 32);
                b[2 * jj][0] = r0; b[2 * jj][1] = r2;
                b[2 * jj + 1][0] = r1; b[2 * jj + 1][1] = r3;
            }
#pragma unroll
            for (int i = 0; i < 4; ++i)
#pragma unroll
                for (int j = 0; j < 8; ++j)
                    mma_f16(acc[i][j], a[i], b[j][0], b[j][1]);
        }
        if (c + 3 < NCHUNK)
            load_stage(smb, (c + 3) & 3, A, B, rowBase, colBase, (c + 3) * 32, tid);
        CP_COMMIT();
    }

    const int lrow = lane >> 2;
#pragma unroll
    for (int i = 0; i < 4; ++i) {
        int r0 = rowBase + warpM * 64 + i * 16 + lrow;
#pragma unroll
        for (int j = 0; j < 8; ++j) {
            int cc = (colBase + warpN * 64 + j * 8 + (lane & 3) * 2) >> 1;
#pragma unroll
            for (int t = 0; t < 2; ++t) {
                int r = r0 + t * 8;
                float vre = acc[i][j][2 * t], vim = acc[i][j][2 * t + 1];
                if (mode == 0) {
                    int s = r >> 2, bb = r & 3;
                    if (cc < 2048) {
                        int h = cc >> 7, m = cc & 127;
                        __half rh, rl, ih, il;
                        split_fp16(vre, rh, rl);
                        split_fp16(vim, ih, il);
                        __half* d = g_qp + ((size_t)(bb * 16 + h) * 1024 + s) * 512;
                        d[m] = rh; d[128 + m] = rl; d[256 + m] = ih; d[384 + m] = il;
                    } else if (cc < 4096) {
                        int u = cc - 2048, h = u >> 7, m = u & 127;
                        __half* d = g_kp + ((size_t)(bb * 16 + h) * 1024 + s) * 256;
                        d[m] = __float2half(vre); d[128 + m] = __float2half(vim);
                    } else {
                        int u = cc - 4096, h = u >> 6, vc = u & 63;
                        __half* d = g_vt + (size_t)(bb * 16 + h) * 128 * 1024;
                        d[(size_t)vc * 1024 + s]        = __float2half(vre);
                        d[(size_t)(64 + vc) * 1024 + s] = __float2half(vim);
                    }
                } else {
                    size_t i0 = (size_t)r * 1024 + cc;
                    Dout[i0]       = vre + xre[i0];
                    Dout[SBE + i0] = vim + xim[i0];
                }
            }
        }
    }
}

// ---------------- HMMA flash attention ------------------------------------------
#define QPITCH 1040
#define KPITCH 528
#define VPITCH 80
#define AT_SMK0 (64 * QPITCH)                 // 66560
#define AT_SMK1 (AT_SMK0 + 32 * KPITCH)       // 83456
#define AT_SMV0 (AT_SMK1 + 32 * KPITCH)       // 100352
#define AT_SMV1 (AT_SMV0 + 128 * VPITCH)      // 110592
#define AT_TOT  (AT_SMV1 + 128 * VPITCH)      // 120832

__device__ __forceinline__ void load_kv(uint32_t smb, int buf,
    const __half* Kg, const __half* Vg, int kt, int tid)
{
    uint32_t kdst = smb + (buf ? AT_SMK1 : AT_SMK0);
    const __half* ksrc = Kg + (size_t)kt * 32 * 256;
#pragma unroll
    for (int i = 0; i < 8; ++i) {
        int c = tid + i * 128, row = c >> 5, seg = c & 31;
        cp_async16(kdst + row * KPITCH + seg * 16, ksrc + (size_t)row * 256 + seg * 8);
    }
    uint32_t vdst = smb + (buf ? AT_SMV1 : AT_SMV0);
#pragma unroll
    for (int i = 0; i < 4; ++i) {
        int c = tid + i * 128, vc = c >> 2, seg = c & 3;
        cp_async16(vdst + vc * VPITCH + seg * 16,
                   Vg + (size_t)vc * 1024 + kt * 32 + seg * 8);
    }
}

__global__ __launch_bounds__(128) void attn_mma()
{
    extern __shared__ char sm[];
    const uint32_t smb = smem_u32(sm);
    const int tid = threadIdx.x, lane = tid & 31, wid = tid >> 5;
    const int qt = 15 - blockIdx.x;
    const int bh = blockIdx.y;
    const int qbase = qt * 64;
    const int nkt = 2 * qt + 2;
    const float scale = 0.088388347648318447f;

    const __half* Qg = g_qp + ((size_t)bh * 1024 + qbase) * 512;
    const __half* Kg = g_kp + (size_t)bh * 1024 * 256;
    const __half* Vg = g_vt + (size_t)bh * 128 * 1024;

#pragma unroll
    for (int i = 0; i < 32; ++i) {
        int c = tid + i * 128, row = c >> 6, seg = c & 63;
        cp_async16(smb + row * QPITCH + seg * 16, Qg + (size_t)row * 512 + seg * 8);
    }
    load_kv(smb, 0, Kg, Vg, 0, tid);
    CP_COMMIT();

    float m0 = -1e30f, m1 = -1e30f, l0 = 0.f, l1 = 0.f;
    float accR[8][4], accI[8][4];
#pragma unroll
    for (int j = 0; j < 8; ++j)
#pragma unroll
        for (int k = 0; k < 4; ++k) { accR[j][k] = 0.f; accI[j][k] = 0.f; }

    const int rowg = qbase + wid * 16 + (lane >> 2);
    const uint32_t aBase = smb + (wid * 16 + (lane & 15)) * QPITCH + (lane >> 4) * 16;

#pragma unroll 1
    for (int kt = 0; kt < nkt; ++kt) {
        if (kt + 1 < nkt) { load_kv(smb, (kt + 1) & 1, Kg, Vg, kt + 1, tid); CP_COMMIT(); CP_WAIT1(); }
        else CP_WAIT0();
        __syncthreads();
        const uint32_t kbuf = smb + ((kt & 1) ? AT_SMK1 : AT_SMK0);
        const uint32_t vbuf = smb + ((kt & 1) ? AT_SMV1 : AT_SMV0);

        float S[4][4][4];
#pragma unroll
        for (int c2 = 0; c2 < 4; ++c2)
#pragma unroll
            for (int n = 0; n < 4; ++n)
#pragma unroll
                for (int q = 0; q < 4; ++q) S[c2][n][q] = 0.f;

        // QK^T: rr,ii,ri,ir; Q split-2, K unsplit -> 8 mma per (ks, ntp)
#pragma unroll
        for (int ks = 0; ks < 8; ++ks) {
            uint32_t arh[4], arl[4], aih[4], ail[4];
            uint32_t aa = aBase + ks * 32;
            ldsm_x4(arh[0], arh[1], arh[2], arh[3], aa);
            ldsm_x4(arl[0], arl[1], arl[2], arl[3], aa + 256);
            ldsm_x4(aih[0], aih[1], aih[2], aih[3], aa + 512);
            ldsm_x4(ail[0], ail[1], ail[2], ail[3], aa + 768);
#pragma unroll
            for (int ntp = 0; ntp < 2; ++ntp) {
                uint32_t ba = kbuf + (ntp * 16 + (lane & 15)) * KPITCH + (lane >> 4) * 16 + ks * 32;
                uint32_t br[4], bi[4];
                ldsm_x4(br[0], br[1], br[2], br[3], ba);
                ldsm_x4(bi[0], bi[1], bi[2], bi[3], ba + 256);
#pragma unroll
                for (int t2 = 0; t2 < 2; ++t2) {
                    int nt = 2 * ntp + t2;
                    mma_f16(S[0][nt], arh, br[t2], br[t2 + 2]);
                    mma_f16(S[0][nt], arl, br[t2], br[t2 + 2]);
                    mma_f16(S[1][nt], aih, bi[t2], bi[t2 + 2]);
                    mma_f16(S[1][nt], ail, bi[t2], bi[t2 + 2]);
                    mma_f16(S[2][nt], arh, bi[t2], bi[t2 + 2]);
                    mma_f16(S[2][nt], arl, bi[t2], bi[t2 + 2]);
                    mma_f16(S[3][nt], aih, br[t2], br[t2 + 2]);
                    mma_f16(S[3][nt], ail, br[t2], br[t2 + 2]);
                }
            }
        }

        // amp (FMA-pipe rsqrt) + causal + online softmax (FMA-pipe exp)
        float mx0 = -1e30f, mx1 = -1e30f;
#pragma unroll
        for (int nt = 0; nt < 4; ++nt)
#pragma unroll
            for (int q = 0; q < 4; ++q) {
                float re = S[0][nt][q] - S[1][nt][q];
                float im = S[2][nt][q] + S[3][nt][q];
                float amp = famp(re, im) * scale;
                int col = kt * 32 + nt * 8 + (lane & 3) * 2 + (q & 1);
                int row = rowg + ((q >> 1) ? 8 : 0);
                float logit = (col <= row) ? amp : -1e30f;
                S[0][nt][q] = logit;
                if (q < 2) mx0 = fmaxf(mx0, logit);
                else       mx1 = fmaxf(mx1, logit);
            }
        mx0 = fmaxf(mx0, __shfl_xor_sync(~0u, mx0, 1));
        mx0 = fmaxf(mx0, __shfl_xor_sync(~0u, mx0, 2));
        mx1 = fmaxf(mx1, __shfl_xor_sync(~0u, mx1, 1));
        mx1 = fmaxf(mx1, __shfl_xor_sync(~0u, mx1, 2));
        float m0n = fmaxf(m0, mx0), m1n = fmaxf(m1, mx1);
        float corr0 = fexp(m0 - m0n), corr1 = fexp(m1 - m1n);
        float ph[4][4], pl[4][4];
        float sum0 = 0.f, sum1 = 0.f;
#pragma unroll
        for (int nt = 0; nt < 4; ++nt)
#pragma unroll
            for (int q = 0; q < 4; ++q) {
                float p = fexp(S[0][nt][q] - ((q < 2) ? m0n : m1n));
                if (q < 2) sum0 += p; else sum1 += p;
                float h = __half2float(__float2half(p));
                ph[nt][q] = h;
                pl[nt][q] = p - h;
            }
        sum0 += __shfl_xor_sync(~0u, sum0, 1);
        sum0 += __shfl_xor_sync(~0u, sum0, 2);
        sum1 += __shfl_xor_sync(~0u, sum1, 1);
        sum1 += __shfl_xor_sync(~0u, sum1, 2);
        l0 = l0 * corr0 + sum0;
        l1 = l1 * corr1 + sum1;
        m0 = m0n; m1 = m1n;
#pragma unroll
        for (int j = 0; j < 8; ++j) {
            accR[j][0] *= corr0; accR[j][1] *= corr0;
            accR[j][2] *= corr1; accR[j][3] *= corr1;
            accI[j][0] *= corr0; accI[j][1] *= corr0;
            accI[j][2] *= corr1; accI[j][3] *= corr1;
        }

        // P*V: P split-2, V unsplit -> 4 mma per (s, pr)
#pragma unroll
        for (int s = 0; s < 2; ++s) {
            uint32_t Ah[4], Al[4];
            Ah[0] = pack_h2(ph[2 * s][0], ph[2 * s][1]);
            Ah[1] = pack_h2(ph[2 * s][2], ph[2 * s][3]);
            Ah[2] = pack_h2(ph[2 * s + 1][0], ph[2 * s + 1][1]);
            Ah[3] = pack_h2(ph[2 * s + 1][2], ph[2 * s + 1][3]);
            Al[0] = pack_h2(pl[2 * s][0], pl[2 * s][1]);
            Al[1] = pack_h2(pl[2 * s][2], pl[2 * s][3]);
            Al[2] = pack_h2(pl[2 * s + 1][0], pl[2 * s + 1][1]);
            Al[3] = pack_h2(pl[2 * s + 1][2], pl[2 * s + 1][3]);
#pragma unroll
            for (int pr = 0; pr < 4; ++pr) {
                uint32_t va = vbuf + (pr * 16 + (lane & 15)) * VPITCH + (lane >> 4) * 16 + s * 32;
                uint32_t vr[4], vi[4];
                ldsm_x4(vr[0], vr[1], vr[2], vr[3], va);
                ldsm_x4(vi[0], vi[1], vi[2], vi[3], va + 64 * VPITCH);
                mma_f16(accR[2 * pr],     Ah, vr[0], vr[2]);
                mma_f16(accR[2 * pr],     Al, vr[0], vr[2]);
                mma_f16(accR[2 * pr + 1], Ah, vr[1], vr[3]);
                mma_f16(accR[2 * pr + 1], Al, vr[1], vr[3]);
                mma_f16(accI[2 * pr],     Ah, vi[0], vi[2]);
                mma_f16(accI[2 * pr],     Al, vi[0], vi[2]);
                mma_f16(accI[2 * pr + 1], Ah, vi[1], vi[3]);
                mma_f16(accI[2 * pr + 1], Al, vi[1], vi[3]);
            }
        }
        __syncthreads();
    }

    // epilogue: normalize + write packed split-fp16 rows for out-GEMM
    const float inv0 = 1.0f / l0, inv1 = 1.0f / l1;
    const int b = bh >> 4, h = bh & 15;
#pragma unroll
    for (int t = 0; t < 2; ++t) {
        int srow = rowg + t * 8;
        size_t r = (size_t)srow * 4 + b;
        float inv = t ? inv1 : inv0;
#pragma unroll
        for (int j = 0; j < 8; ++j)
#pragma unroll
            for (int e2 = 0; e2 < 2; ++e2) {
                int vc = j * 8 + (lane & 3) * 2 + e2;
                float re = accR[j][2 * t + e2] * inv;
                float im = accI[j][2 * t + e2] * inv;
                __half rh, rl, ih, il;
                split_fp16(re, rh, rl);
                split_fp16(im, ih, il);
                __half* p = g_Aatt + r * GK + (h * 64 + vc);
                p[0] = rh; p[1024] = rl; p[2048] = ih; p[3072] = il;
            }
    }
}

// ---------------------------------------------------------------------------
extern "C" void kernel_launch(void* const* d_in, const int* in_sizes, int n_in,
                              void* d_out, int out_size)
{
    const float* xre = (const float*)d_in[0];
    const float* xim = (const float*)d_in[1];
    float* out = (float*)d_out;

    const int gemm_smem = 4 * STAGEB;
    static bool attr_set = false;
    if (!attr_set) {
        cudaFuncSetAttribute(gemm_hmma,
                             cudaFuncAttributeMaxDynamicSharedMemorySize, gemm_smem);
        cudaFuncSetAttribute(attn_mma,
                             cudaFuncAttributeMaxDynamicSharedMemorySize, AT_TOT);
        attr_set = true;
    }

    pack_A_proj<<<16384, 256>>>(xre, xim);
    pack_B_proj<<<20480, 256>>>((const float*)d_in[2], (const float*)d_in[3],
                                (const float*)d_in[4], (const float*)d_in[5],
                                (const float*)d_in[6], (const float*)d_in[7]);
    pack_B_out<<<4096, 256>>>((const float*)d_in[8], (const float*)d_in[9]);

    gemm_hmma<<<dim3(32, 40), 256, gemm_smem>>>(0, nullptr, nullptr, nullptr);

    attn_mma<<<dim3(16, 64), 128, AT_TOT>>>();

    gemm_hmma<<<dim3(32, 8), 256, gemm_smem>>>(1, out, xre, xim);
}

// round 8
// speedup vs baseline: 3.4896x; 1.1093x over previous
#include <cuda_runtime.h>
#include <cuda_fp16.h>
#include <cstdint>
#include <math.h>

#define Ssz 1024
#define Bsz 4
#define Esz 1024
#define SBE (Ssz * Bsz * Esz)
#define GK  4096                    // 4 planes x 1024 (fp16 2-term split)
#define NCHUNK (GK / 32)            // 128

// ---------------- scratch -----------------------------------------------------
__device__ __align__(16) __half g_Aproj[4096u * GK];
__device__ __align__(16) __half g_Bproj[10240u * GK];
__device__ __align__(16) __half g_Bout [2048u * GK];
__device__ __align__(16) __half g_Aatt [4096u * GK];
__device__ __align__(16) __half g_qp[64u * 1024 * 512]; // [bh][s][qr_h|qr_l|qi_h|qi_l]
__device__ __align__(16) __half g_kp[64u * 1024 * 256]; // [bh][t][kr_h|ki_h]
__device__ __align__(16) __half g_vt[64u * 128 * 1024]; // [bh][vr(64)|vi(64) planes][t]

// ---------------- helpers ------------------------------------------------------
__device__ __forceinline__ uint32_t smem_u32(const void* p) {
    uint32_t a;
    asm("{ .reg .u64 t; cvta.to.shared.u64 t, %1; cvt.u32.u64 %0, t; }" : "=r"(a) : "l"(p));
    return a;
}
__device__ __forceinline__ void cp_async16(uint32_t dst, const void* src) {
    asm volatile("cp.async.cg.shared.global [%0], [%1], 16;" :: "r"(dst), "l"(src) : "memory");
}
#define CP_COMMIT() asm volatile("cp.async.commit_group;" ::: "memory")
#define CP_WAIT0()  asm volatile("cp.async.wait_group 0;" ::: "memory")
#define CP_WAIT1()  asm volatile("cp.async.wait_group 1;" ::: "memory")
#define CP_WAIT2()  asm volatile("cp.async.wait_group 2;" ::: "memory")

__device__ __forceinline__ void ldsm_x4(uint32_t& r0, uint32_t& r1,
                                        uint32_t& r2, uint32_t& r3, uint32_t a) {
    asm volatile("ldmatrix.sync.aligned.m8n8.x4.shared.b16 {%0,%1,%2,%3}, [%4];"
                 : "=r"(r0), "=r"(r1), "=r"(r2), "=r"(r3) : "r"(a));
}
__device__ __forceinline__ void mma_f16(float* d, const uint32_t* a,
                                        uint32_t b0, uint32_t b1) {
    asm volatile(
        "mma.sync.aligned.m16n8k16.row.col.f32.f16.f16.f32 "
        "{%0,%1,%2,%3}, {%4,%5,%6,%7}, {%8,%9}, {%0,%1,%2,%3};"
        : "+f"(d[0]), "+f"(d[1]), "+f"(d[2]), "+f"(d[3])
        : "r"(a[0]), "r"(a[1]), "r"(a[2]), "r"(a[3]), "r"(b0), "r"(b1));
}
__device__ __forceinline__ void split_fp16(float x, __half& h, __half& l) {
    h = __float2half(x);
    l = __float2half(x - __half2float(h));
}
__device__ __forceinline__ uint32_t pack_h2(float lo, float hi) {
    uint32_t r;
    asm("cvt.rn.f16x2.f32 %0, %1, %2;" : "=r"(r) : "f"(hi), "f"(lo));
    return r;
}
// e^x for x <= ~0, FMA-pipe only (no MUFU)
__device__ __forceinline__ float fexp(float x) {
    float t = fmaxf(x * 1.4426950408889634f, -126.0f);
    int k = __float2int_rn(t);
    float f = (t - (float)k) * 0.6931471805599453f;
    float p = 1.0f + f * (1.0f + f * (0.5f + f * (0.16666667f +
                   f * (0.041666667f + f * 0.0083333333f))));
    return p * __int_as_float((k + 127) << 23);
}
// sqrt(re^2+im^2) via bit-hack rsqrt + 2 Newton iters (no MUFU)
__device__ __forceinline__ float famp(float re, float im) {
    float z = fmaf(re, re, im * im);
    z = fmaxf(z, 1e-37f);
    float r = __int_as_float(0x5f3759df - (__float_as_int(z) >> 1));
    r = r * fmaf(-0.5f * z * r, r, 1.5f);
    r = r * fmaf(-0.5f * z * r, r, 1.5f);
    return z * r;
}

// ---------------- pack kernels --------------------------------------------------
__global__ __launch_bounds__(256) void pack_A_proj(
    const float* __restrict__ xre, const float* __restrict__ xim)
{
    int idx = blockIdx.x * 256 + threadIdx.x;
    int r = idx >> 10, e = idx & 1023;
    __half rh, rl, ih, il;
    split_fp16(xre[idx], rh, rl);
    split_fp16(xim[idx], ih, il);
    __half* p = g_Aproj + (size_t)r * GK + e;
    p[0] = rh; p[1024] = rl; p[2048] = ih; p[3072] = il;
}

// B rows: real out = [wrh, wrh, -wih, -wih]; imag out = [wih, wih, wrh, wrh]
__device__ __forceinline__ void write_B_rows(__half* base, size_t n_re,
                                             int e, float wr, float wi)
{
    __half rh = __float2half(wr);
    __half ih = __float2half(wi);
    __half nih = __hneg(ih);
    __half* pr = base + n_re * GK + e;
    pr[0] = rh; pr[1024] = rh; pr[2048] = nih; pr[3072] = nih;
    __half* pi = base + (n_re + 1) * GK + e;
    pi[0] = ih; pi[1024] = ih; pi[2048] = rh; pi[3072] = rh;
}

__global__ __launch_bounds__(256) void pack_B_proj(
    const float* __restrict__ wq_re, const float* __restrict__ wq_im,
    const float* __restrict__ wk_re, const float* __restrict__ wk_im,
    const float* __restrict__ wv_re, const float* __restrict__ wv_im)
{
    int idx = blockIdx.x * 256 + threadIdx.x;
    int c = idx >> 10, e = idx & 1023;
    const float *wre, *wim; size_t off;
    if (c < 2048)      { wre = wq_re; wim = wq_im; off = (size_t)c * 1024 + e; }
    else if (c < 4096) { wre = wk_re; wim = wk_im; off = (size_t)(c - 2048) * 1024 + e; }
    else               { wre = wv_re; wim = wv_im; off = (size_t)(c - 4096) * 1024 + e; }
    write_B_rows(g_Bproj, (size_t)(2 * c), e, wre[off], wim[off]);
}

__global__ __launch_bounds__(256) void pack_B_out(
    const float* __restrict__ wo_re, const float* __restrict__ wo_im)
{
    int idx = blockIdx.x * 256 + threadIdx.x;
    int f = idx >> 10, e = idx & 1023;
    write_B_rows(g_Bout, (size_t)(2 * f), e,
                 wo_re[(size_t)e * 1024 + f], wo_im[(size_t)e * 1024 + f]);
}

// ---------------- HMMA GEMM (128x256 tile, K-chunk 32, 4 stages, 512 thr) ------
#define ROWB   80
#define STAGEB (384 * ROWB)
#define BOFF   (128 * ROWB)

__device__ __forceinline__ void load_stage(
    uint32_t smb, int stage, const __half* A, const __half* B,
    int rowBase, int colBase, int kk, int tid)
{
    uint32_t base = smb + stage * STAGEB;
    {   // A: 512 x 16B, one op per thread
        int row = tid >> 2, seg = tid & 3;
        cp_async16(base + row * ROWB + seg * 16,
                   A + (size_t)(rowBase + row) * GK + kk + seg * 8);
    }
#pragma unroll
    for (int i = 0; i < 2; ++i) {   // B: 1024 x 16B
        int v = tid + i * 512, row = v >> 2, seg = v & 3;
        cp_async16(base + BOFF + row * ROWB + seg * 16,
                   B + (size_t)(colBase + row) * GK + kk + seg * 8);
    }
}

__global__ __launch_bounds__(512, 1) void gemm_hmma(
    int mode, float* __restrict__ Dout,
    const float* __restrict__ xre, const float* __restrict__ xim)
{
    extern __shared__ char sm[];
    const uint32_t smb = smem_u32(sm);
    const int tid = threadIdx.x;
    const int wid = tid >> 5, lane = tid & 31;
    const int warpM = wid >> 2, warpN = wid & 3;      // 4 x 4 warps
    const int rowBase = blockIdx.x * 128;
    const int colBase = blockIdx.y * 256;
    const __half* A = mode ? g_Aatt : g_Aproj;
    const __half* B = mode ? g_Bout : g_Bproj;

    float acc[2][8][4];                               // warp tile 32x64
#pragma unroll
    for (int i = 0; i < 2; ++i)
#pragma unroll
        for (int j = 0; j < 8; ++j)
#pragma unroll
            for (int k = 0; k < 4; ++k) acc[i][j][k] = 0.f;

    load_stage(smb, 0, A, B, rowBase, colBase, 0, tid);  CP_COMMIT();
    load_stage(smb, 1, A, B, rowBase, colBase, 32, tid); CP_COMMIT();
    load_stage(smb, 2, A, B, rowBase, colBase, 64, tid); CP_COMMIT();

    const uint32_t aRowAddr = smb + (warpM * 32 + (lane & 15)) * ROWB + (lane >> 4) * 16;
    const uint32_t bRowAddr = smb + BOFF + (warpN * 64 + (lane & 15)) * ROWB + (lane >> 4) * 16;

#pragma unroll 1
    for (int c = 0; c < NCHUNK; ++c) {
        CP_WAIT2();
        __syncthreads();
        const uint32_t stoff = (c & 3) * STAGEB;
#pragma unroll
        for (int s = 0; s < 2; ++s) {
            uint32_t a[2][4], b[8][2];
#pragma unroll
            for (int i = 0; i < 2; ++i)
                ldsm_x4(a[i][0], a[i][1], a[i][2], a[i][3],
                        aRowAddr + stoff + i * 16 * ROWB + s * 32);
#pragma unroll
            for (int jj = 0; jj < 4; ++jj) {
                uint32_t r0, r1, r2, r3;
                ldsm_x4(r0, r1, r2, r3, bRowAddr + stoff + jj * 16 * ROWB + s * 32);
                b[2 * jj][0] = r0; b[2 * jj][1] = r2;
                b[2 * jj + 1][0] = r1; b[2 * jj + 1][1] = r3;
            }
#pragma unroll
            for (int i = 0; i < 2; ++i)
#pragma unroll
                for (int j = 0; j < 8; ++j)
                    mma_f16(acc[i][j], a[i], b[j][0], b[j][1]);
        }
        if (c + 3 < NCHUNK)
            load_stage(smb, (c + 3) & 3, A, B, rowBase, colBase, (c + 3) * 32, tid);
        CP_COMMIT();
    }

    const int lrow = lane >> 2;
#pragma unroll
    for (int i = 0; i < 2; ++i) {
        int r0 = rowBase + warpM * 32 + i * 16 + lrow;
#pragma unroll
        for (int j = 0; j < 8; ++j) {
            int cc = (colBase + warpN * 64 + j * 8 + (lane & 3) * 2) >> 1;
#pragma unroll
            for (int t = 0; t < 2; ++t) {
                int r = r0 + t * 8;
                float vre = acc[i][j][2 * t], vim = acc[i][j][2 * t + 1];
                if (mode == 0) {
                    int s = r >> 2, bb = r & 3;
                    if (cc < 2048) {
                        int h = cc >> 7, m = cc & 127;
                        __half rh, rl, ih, il;
                        split_fp16(vre, rh, rl);
                        split_fp16(vim, ih, il);
                        __half* d = g_qp + ((size_t)(bb * 16 + h) * 1024 + s) * 512;
                        d[m] = rh; d[128 + m] = rl; d[256 + m] = ih; d[384 + m] = il;
                    } else if (cc < 4096) {
                        int u = cc - 2048, h = u >> 7, m = u & 127;
                        __half* d = g_kp + ((size_t)(bb * 16 + h) * 1024 + s) * 256;
                        d[m] = __float2half(vre); d[128 + m] = __float2half(vim);
                    } else {
                        int u = cc - 4096, h = u >> 6, vc = u & 63;
                        __half* d = g_vt + (size_t)(bb * 16 + h) * 128 * 1024;
                        d[(size_t)vc * 1024 + s]        = __float2half(vre);
                        d[(size_t)(64 + vc) * 1024 + s] = __float2half(vim);
                    }
                } else {
                    size_t i0 = (size_t)r * 1024 + cc;
                    Dout[i0]       = vre + xre[i0];
                    Dout[SBE + i0] = vim + xim[i0];
                }
            }
        }
    }
}

// ---------------- HMMA flash attention (unchanged from R7) ----------------------
#define QPITCH 1040
#define KPITCH 528
#define VPITCH 80
#define AT_SMK0 (64 * QPITCH)
#define AT_SMK1 (AT_SMK0 + 32 * KPITCH)
#define AT_SMV0 (AT_SMK1 + 32 * KPITCH)
#define AT_SMV1 (AT_SMV0 + 128 * VPITCH)
#define AT_TOT  (AT_SMV1 + 128 * VPITCH)

__device__ __forceinline__ void load_kv(uint32_t smb, int buf,
    const __half* Kg, const __half* Vg, int kt, int tid)
{
    uint32_t kdst = smb + (buf ? AT_SMK1 : AT_SMK0);
    const __half* ksrc = Kg + (size_t)kt * 32 * 256;
#pragma unroll
    for (int i = 0; i < 8; ++i) {
        int c = tid + i * 128, row = c >> 5, seg = c & 31;
        cp_async16(kdst + row * KPITCH + seg * 16, ksrc + (size_t)row * 256 + seg * 8);
    }
    uint32_t vdst = smb + (buf ? AT_SMV1 : AT_SMV0);
#pragma unroll
    for (int i = 0; i < 4; ++i) {
        int c = tid + i * 128, vc = c >> 2, seg = c & 3;
        cp_async16(vdst + vc * VPITCH + seg * 16,
                   Vg + (size_t)vc * 1024 + kt * 32 + seg * 8);
    }
}

__global__ __launch_bounds__(128) void attn_mma()
{
    extern __shared__ char sm[];
    const uint32_t smb = smem_u32(sm);
    const int tid = threadIdx.x, lane = tid & 31, wid = tid >> 5;
    const int qt = 15 - blockIdx.x;
    const int bh = blockIdx.y;
    const int qbase = qt * 64;
    const int nkt = 2 * qt + 2;
    const float scale = 0.088388347648318447f;

    const __half* Qg = g_qp + ((size_t)bh * 1024 + qbase) * 512;
    const __half* Kg = g_kp + (size_t)bh * 1024 * 256;
    const __half* Vg = g_vt + (size_t)bh * 128 * 1024;

#pragma unroll
    for (int i = 0; i < 32; ++i) {
        int c = tid + i * 128, row = c >> 6, seg = c & 63;
        cp_async16(smb + row * QPITCH + seg * 16, Qg + (size_t)row * 512 + seg * 8);
    }
    load_kv(smb, 0, Kg, Vg, 0, tid);
    CP_COMMIT();

    float m0 = -1e30f, m1 = -1e30f, l0 = 0.f, l1 = 0.f;
    float accR[8][4], accI[8][4];
#pragma unroll
    for (int j = 0; j < 8; ++j)
#pragma unroll
        for (int k = 0; k < 4; ++k) { accR[j][k] = 0.f; accI[j][k] = 0.f; }

    const int rowg = qbase + wid * 16 + (lane >> 2);
    const uint32_t aBase = smb + (wid * 16 + (lane & 15)) * QPITCH + (lane >> 4) * 16;

#pragma unroll 1
    for (int kt = 0; kt < nkt; ++kt) {
        if (kt + 1 < nkt) { load_kv(smb, (kt + 1) & 1, Kg, Vg, kt + 1, tid); CP_COMMIT(); CP_WAIT1(); }
        else CP_WAIT0();
        __syncthreads();
        const uint32_t kbuf = smb + ((kt & 1) ? AT_SMK1 : AT_SMK0);
        const uint32_t vbuf = smb + ((kt & 1) ? AT_SMV1 : AT_SMV0);

        float S[4][4][4];
#pragma unroll
        for (int c2 = 0; c2 < 4; ++c2)
#pragma unroll
            for (int n = 0; n < 4; ++n)
#pragma unroll
                for (int q = 0; q < 4; ++q) S[c2][n][q] = 0.f;

#pragma unroll
        for (int ks = 0; ks < 8; ++ks) {
            uint32_t arh[4], arl[4], aih[4], ail[4];
            uint32_t aa = aBase + ks * 32;
            ldsm_x4(arh[0], arh[1], arh[2], arh[3], aa);
            ldsm_x4(arl[0], arl[1], arl[2], arl[3], aa + 256);
            ldsm_x4(aih[0], aih[1], aih[2], aih[3], aa + 512);
            ldsm_x4(ail[0], ail[1], ail[2], ail[3], aa + 768);
#pragma unroll
            for (int ntp = 0; ntp < 2; ++ntp) {
                uint32_t ba = kbuf + (ntp * 16 + (lane & 15)) * KPITCH + (lane >> 4) * 16 + ks * 32;
                uint32_t br[4], bi[4];
                ldsm_x4(br[0], br[1], br[2], br[3], ba);
                ldsm_x4(bi[0], bi[1], bi[2], bi[3], ba + 256);
#pragma unroll
                for (int t2 = 0; t2 < 2; ++t2) {
                    int nt = 2 * ntp + t2;
                    mma_f16(S[0][nt], arh, br[t2], br[t2 + 2]);
                    mma_f16(S[0][nt], arl, br[t2], br[t2 + 2]);
                    mma_f16(S[1][nt], aih, bi[t2], bi[t2 + 2]);
                    mma_f16(S[1][nt], ail, bi[t2], bi[t2 + 2]);
                    mma_f16(S[2][nt], arh, bi[t2], bi[t2 + 2]);
                    mma_f16(S[2][nt], arl, bi[t2], bi[t2 + 2]);
                    mma_f16(S[3][nt], aih, br[t2], br[t2 + 2]);
                    mma_f16(S[3][nt], ail, br[t2], br[t2 + 2]);
                }
            }
        }

        float mx0 = -1e30f, mx1 = -1e30f;
#pragma unroll
        for (int nt = 0; nt < 4; ++nt)
#pragma unroll
            for (int q = 0; q < 4; ++q) {
                float re = S[0][nt][q] - S[1][nt][q];
                float im = S[2][nt][q] + S[3][nt][q];
                float amp = famp(re, im) * scale;
                int col = kt * 32 + nt * 8 + (lane & 3) * 2 + (q & 1);
                int row = rowg + ((q >> 1) ? 8 : 0);
                float logit = (col <= row) ? amp : -1e30f;
                S[0][nt][q] = logit;
                if (q < 2) mx0 = fmaxf(mx0, logit);
                else       mx1 = fmaxf(mx1, logit);
            }
        mx0 = fmaxf(mx0, __shfl_xor_sync(~0u, mx0, 1));
        mx0 = fmaxf(mx0, __shfl_xor_sync(~0u, mx0, 2));
        mx1 = fmaxf(mx1, __shfl_xor_sync(~0u, mx1, 1));
        mx1 = fmaxf(mx1, __shfl_xor_sync(~0u, mx1, 2));
        float m0n = fmaxf(m0, mx0), m1n = fmaxf(m1, mx1);
        float corr0 = fexp(m0 - m0n), corr1 = fexp(m1 - m1n);
        float ph[4][4], pl[4][4];
        float sum0 = 0.f, sum1 = 0.f;
#pragma unroll
        for (int nt = 0; nt < 4; ++nt)
#pragma unroll
            for (int q = 0; q < 4; ++q) {
                float p = fexp(S[0][nt][q] - ((q < 2) ? m0n : m1n));
                if (q < 2) sum0 += p; else sum1 += p;
                float h = __half2float(__float2half(p));
                ph[nt][q] = h;
                pl[nt][q] = p - h;
            }
        sum0 += __shfl_xor_sync(~0u, sum0, 1);
        sum0 += __shfl_xor_sync(~0u, sum0, 2);
        sum1 += __shfl_xor_sync(~0u, sum1, 1);
        sum1 += __shfl_xor_sync(~0u, sum1, 2);
        l0 = l0 * corr0 + sum0;
        l1 = l1 * corr1 + sum1;
        m0 = m0n; m1 = m1n;
#pragma unroll
        for (int j = 0; j < 8; ++j) {
            accR[j][0] *= corr0; accR[j][1] *= corr0;
            accR[j][2] *= corr1; accR[j][3] *= corr1;
            accI[j][0] *= corr0; accI[j][1] *= corr0;
            accI[j][2] *= corr1; accI[j][3] *= corr1;
        }

#pragma unroll
        for (int s = 0; s < 2; ++s) {
            uint32_t Ah[4], Al[4];
            Ah[0] = pack_h2(ph[2 * s][0], ph[2 * s][1]);
            Ah[1] = pack_h2(ph[2 * s][2], ph[2 * s][3]);
            Ah[2] = pack_h2(ph[2 * s + 1][0], ph[2 * s + 1][1]);
            Ah[3] = pack_h2(ph[2 * s + 1][2], ph[2 * s + 1][3]);
            Al[0] = pack_h2(pl[2 * s][0], pl[2 * s][1]);
            Al[1] = pack_h2(pl[2 * s][2], pl[2 * s][3]);
            Al[2] = pack_h2(pl[2 * s + 1][0], pl[2 * s + 1][1]);
            Al[3] = pack_h2(pl[2 * s + 1][2], pl[2 * s + 1][3]);
#pragma unroll
            for (int pr = 0; pr < 4; ++pr) {
                uint32_t va = vbuf + (pr * 16 + (lane & 15)) * VPITCH + (lane >> 4) * 16 + s * 32;
                uint32_t vr[4], vi[4];
                ldsm_x4(vr[0], vr[1], vr[2], vr[3], va);
                ldsm_x4(vi[0], vi[1], vi[2], vi[3], va + 64 * VPITCH);
                mma_f16(accR[2 * pr],     Ah, vr[0], vr[2]);
                mma_f16(accR[2 * pr],     Al, vr[0], vr[2]);
                mma_f16(accR[2 * pr + 1], Ah, vr[1], vr[3]);
                mma_f16(accR[2 * pr + 1], Al, vr[1], vr[3]);
                mma_f16(accI[2 * pr],     Ah, vi[0], vi[2]);
                mma_f16(accI[2 * pr],     Al, vi[0], vi[2]);
                mma_f16(accI[2 * pr + 1], Ah, vi[1], vi[3]);
                mma_f16(accI[2 * pr + 1], Al, vi[1], vi[3]);
            }
        }
        __syncthreads();
    }

    const float inv0 = 1.0f / l0, inv1 = 1.0f / l1;
    const int b = bh >> 4, h = bh & 15;
#pragma unroll
    for (int t = 0; t < 2; ++t) {
        int srow = rowg + t * 8;
        size_t r = (size_t)srow * 4 + b;
        float inv = t ? inv1 : inv0;
#pragma unroll
        for (int j = 0; j < 8; ++j)
#pragma unroll
            for (int e2 = 0; e2 < 2; ++e2) {
                int vc = j * 8 + (lane & 3) * 2 + e2;
                float re = accR[j][2 * t + e2] * inv;
                float im = accI[j][2 * t + e2] * inv;
                __half rh, rl, ih, il;
                split_fp16(re, rh, rl);
                split_fp16(im, ih, il);
                __half* p = g_Aatt + r * GK + (h * 64 + vc);
                p[0] = rh; p[1024] = rl; p[2048] = ih; p[3072] = il;
            }
    }
}

// ---------------------------------------------------------------------------
extern "C" void kernel_launch(void* const* d_in, const int* in_sizes, int n_in,
                              void* d_out, int out_size)
{
    const float* xre = (const float*)d_in[0];
    const float* xim = (const float*)d_in[1];
    float* out = (float*)d_out;

    const int gemm_smem = 4 * STAGEB;
    static bool attr_set = false;
    if (!attr_set) {
        cudaFuncSetAttribute(gemm_hmma,
                             cudaFuncAttributeMaxDynamicSharedMemorySize, gemm_smem);
        cudaFuncSetAttribute(attn_mma,
                             cudaFuncAttributeMaxDynamicSharedMemorySize, AT_TOT);
        attr_set = true;
    }

    pack_A_proj<<<16384, 256>>>(xre, xim);
    pack_B_proj<<<20480, 256>>>((const float*)d_in[2], (const float*)d_in[3],
                                (const float*)d_in[4], (const float*)d_in[5],
                                (const float*)d_in[6], (const float*)d_in[7]);
    pack_B_out<<<4096, 256>>>((const float*)d_in[8], (const float*)d_in[9]);

    gemm_hmma<<<dim3(32, 40), 512, gemm_smem>>>(0, nullptr, nullptr, nullptr);

    attn_mma<<<dim3(16, 64), 128, AT_TOT>>>();

    gemm_hmma<<<dim3(32, 8), 512, gemm_smem>>>(1, out, xre, xim);
}

// round 9
// speedup vs baseline: 6.3997x; 1.8339x over previous
#include <cuda_runtime.h>
#include <cuda_fp16.h>
#include <cstdint>
#include <math.h>

#define Ssz 1024
#define Bsz 4
#define Esz 1024
#define SBE (Ssz * Bsz * Esz)
#define GK  2048                    // 2 planes x 1024 (plain fp16)
#define NCHUNK (GK / 32)            // 64

// ---------------- scratch -----------------------------------------------------
__device__ __align__(16) __half g_Aproj[4096u * GK];
__device__ __align__(16) __half g_Bproj[10240u * GK];
__device__ __align__(16) __half g_Bout [2048u * GK];
__device__ __align__(16) __half g_Aatt [4096u * GK];
__device__ __align__(16) __half g_qp[64u * 1024 * 256]; // [bh][s][qr(128)|qi(128)]
__device__ __align__(16) __half g_kp[64u * 1024 * 256]; // [bh][t][kr|ki]
__device__ __align__(16) __half g_vt[64u * 128 * 1024]; // [bh][vr(64)|vi(64) planes][t]

// ---------------- helpers ------------------------------------------------------
__device__ __forceinline__ uint32_t smem_u32(const void* p) {
    uint32_t a;
    asm("{ .reg .u64 t; cvta.to.shared.u64 t, %1; cvt.u32.u64 %0, t; }" : "=r"(a) : "l"(p));
    return a;
}
__device__ __forceinline__ void cp_async16(uint32_t dst, const void* src) {
    asm volatile("cp.async.cg.shared.global [%0], [%1], 16;" :: "r"(dst), "l"(src) : "memory");
}
#define CP_COMMIT() asm volatile("cp.async.commit_group;" ::: "memory")
#define CP_WAIT0()  asm volatile("cp.async.wait_group 0;" ::: "memory")
#define CP_WAIT1()  asm volatile("cp.async.wait_group 1;" ::: "memory")
#define CP_WAIT2()  asm volatile("cp.async.wait_group 2;" ::: "memory")

__device__ __forceinline__ void ldsm_x4(uint32_t& r0, uint32_t& r1,
                                        uint32_t& r2, uint32_t& r3, uint32_t a) {
    asm volatile("ldmatrix.sync.aligned.m8n8.x4.shared.b16 {%0,%1,%2,%3}, [%4];"
                 : "=r"(r0), "=r"(r1), "=r"(r2), "=r"(r3) : "r"(a));
}
__device__ __forceinline__ void mma_f16(float* d, const uint32_t* a,
                                        uint32_t b0, uint32_t b1) {
    asm volatile(
        "mma.sync.aligned.m16n8k16.row.col.f32.f16.f16.f32 "
        "{%0,%1,%2,%3}, {%4,%5,%6,%7}, {%8,%9}, {%0,%1,%2,%3};"
        : "+f"(d[0]), "+f"(d[1]), "+f"(d[2]), "+f"(d[3])
        : "r"(a[0]), "r"(a[1]), "r"(a[2]), "r"(a[3]), "r"(b0), "r"(b1));
}
__device__ __forceinline__ uint32_t pack_h2(float lo, float hi) {
    uint32_t r;
    asm("cvt.rn.f16x2.f32 %0, %1, %2;" : "=r"(r) : "f"(hi), "f"(lo));
    return r;
}
// e^x for x <= ~0, FMA-pipe only (no MUFU)
__device__ __forceinline__ float fexp(float x) {
    float t = fmaxf(x * 1.4426950408889634f, -126.0f);
    int k = __float2int_rn(t);
    float f = (t - (float)k) * 0.6931471805599453f;
    float p = 1.0f + f * (1.0f + f * (0.5f + f * (0.16666667f +
                   f * (0.041666667f + f * 0.0083333333f))));
    return p * __int_as_float((k + 127) << 23);
}
// sqrt(re^2+im^2) via bit-hack rsqrt + 2 Newton iters (no MUFU)
__device__ __forceinline__ float famp(float re, float im) {
    float z = fmaf(re, re, im * im);
    z = fmaxf(z, 1e-37f);
    float r = __int_as_float(0x5f3759df - (__float_as_int(z) >> 1));
    r = r * fmaf(-0.5f * z * r, r, 1.5f);
    r = r * fmaf(-0.5f * z * r, r, 1.5f);
    return z * r;
}

// ---------------- pack kernels --------------------------------------------------
__global__ __launch_bounds__(256) void pack_A_proj(
    const float* __restrict__ xre, const float* __restrict__ xim)
{
    int idx = blockIdx.x * 256 + threadIdx.x;
    int r = idx >> 10, e = idx & 1023;
    __half* p = g_Aproj + (size_t)r * GK + e;
    p[0] = __float2half(xre[idx]);
    p[1024] = __float2half(xim[idx]);
}

// B rows: real out = [wr, -wi]; imag out = [wi, wr]
__device__ __forceinline__ void write_B_rows(__half* base, size_t n_re,
                                             int e, float wr, float wi)
{
    __half rh = __float2half(wr);
    __half ih = __float2half(wi);
    __half* pr = base + n_re * GK + e;
    pr[0] = rh; pr[1024] = __hneg(ih);
    __half* pi = base + (n_re + 1) * GK + e;
    pi[0] = ih; pi[1024] = rh;
}

__global__ __launch_bounds__(256) void pack_B_proj(
    const float* __restrict__ wq_re, const float* __restrict__ wq_im,
    const float* __restrict__ wk_re, const float* __restrict__ wk_im,
    const float* __restrict__ wv_re, const float* __restrict__ wv_im)
{
    int idx = blockIdx.x * 256 + threadIdx.x;
    int c = idx >> 10, e = idx & 1023;
    const float *wre, *wim; size_t off;
    if (c < 2048)      { wre = wq_re; wim = wq_im; off = (size_t)c * 1024 + e; }
    else if (c < 4096) { wre = wk_re; wim = wk_im; off = (size_t)(c - 2048) * 1024 + e; }
    else               { wre = wv_re; wim = wv_im; off = (size_t)(c - 4096) * 1024 + e; }
    write_B_rows(g_Bproj, (size_t)(2 * c), e, wre[off], wim[off]);
}

__global__ __launch_bounds__(256) void pack_B_out(
    const float* __restrict__ wo_re, const float* __restrict__ wo_im)
{
    int idx = blockIdx.x * 256 + threadIdx.x;
    int f = idx >> 10, e = idx & 1023;
    write_B_rows(g_Bout, (size_t)(2 * f), e,
                 wo_re[(size_t)e * 1024 + f], wo_im[(size_t)e * 1024 + f]);
}

// ---------------- HMMA GEMM (128x256 tile, K-chunk 32, 4 stages, 512 thr) ------
#define ROWB   80
#define STAGEB (384 * ROWB)
#define BOFF   (128 * ROWB)

__device__ __forceinline__ void load_stage(
    uint32_t smb, int stage, const __half* A, const __half* B,
    int rowBase, int colBase, int kk, int tid)
{
    uint32_t base = smb + stage * STAGEB;
    {   // A: 512 x 16B
        int row = tid >> 2, seg = tid & 3;
        cp_async16(base + row * ROWB + seg * 16,
                   A + (size_t)(rowBase + row) * GK + kk + seg * 8);
    }
#pragma unroll
    for (int i = 0; i < 2; ++i) {   // B: 1024 x 16B
        int v = tid + i * 512, row = v >> 2, seg = v & 3;
        cp_async16(base + BOFF + row * ROWB + seg * 16,
                   B + (size_t)(colBase + row) * GK + kk + seg * 8);
    }
}

__global__ __launch_bounds__(512, 1) void gemm_hmma(
    int mode, float* __restrict__ Dout,
    const float* __restrict__ xre, const float* __restrict__ xim)
{
    extern __shared__ char sm[];
    const uint32_t smb = smem_u32(sm);
    const int tid = threadIdx.x;
    const int wid = tid >> 5, lane = tid & 31;
    const int warpM = wid >> 2, warpN = wid & 3;      // 4 x 4 warps
    const int rowBase = blockIdx.x * 128;
    const int colBase = blockIdx.y * 256;
    const __half* A = mode ? g_Aatt : g_Aproj;
    const __half* B = mode ? g_Bout : g_Bproj;

    float acc[2][8][4];                               // warp tile 32x64
#pragma unroll
    for (int i = 0; i < 2; ++i)
#pragma unroll
        for (int j = 0; j < 8; ++j)
#pragma unroll
            for (int k = 0; k < 4; ++k) acc[i][j][k] = 0.f;

    load_stage(smb, 0, A, B, rowBase, colBase, 0, tid);  CP_COMMIT();
    load_stage(smb, 1, A, B, rowBase, colBase, 32, tid); CP_COMMIT();
    load_stage(smb, 2, A, B, rowBase, colBase, 64, tid); CP_COMMIT();

    const uint32_t aRowAddr = smb + (warpM * 32 + (lane & 15)) * ROWB + (lane >> 4) * 16;
    const uint32_t bRowAddr = smb + BOFF + (warpN * 64 + (lane & 15)) * ROWB + (lane >> 4) * 16;

#pragma unroll 1
    for (int c = 0; c < NCHUNK; ++c) {
        CP_WAIT2();
        __syncthreads();
        const uint32_t stoff = (c & 3) * STAGEB;
#pragma unroll
        for (int s = 0; s < 2; ++s) {
            uint32_t a[2][4], b[8][2];
#pragma unroll
            for (int i = 0; i < 2; ++i)
                ldsm_x4(a[i][0], a[i][1], a[i][2], a[i][3],
                        aRowAddr + stoff + i * 16 * ROWB + s * 32);
#pragma unroll
            for (int jj = 0; jj < 4; ++jj) {
                uint32_t r0, r1, r2, r3;
                ldsm_x4(r0, r1, r2, r3, bRowAddr + stoff + jj * 16 * ROWB + s * 32);
                b[2 * jj][0] = r0; b[2 * jj][1] = r2;
                b[2 * jj + 1][0] = r1; b[2 * jj + 1][1] = r3;
            }
#pragma unroll
            for (int i = 0; i < 2; ++i)
#pragma unroll
                for (int j = 0; j < 8; ++j)
                    mma_f16(acc[i][j], a[i], b[j][0], b[j][1]);
        }
        if (c + 3 < NCHUNK)
            load_stage(smb, (c + 3) & 3, A, B, rowBase, colBase, (c + 3) * 32, tid);
        CP_COMMIT();
    }

    const int lrow = lane >> 2;
#pragma unroll
    for (int i = 0; i < 2; ++i) {
        int r0 = rowBase + warpM * 32 + i * 16 + lrow;
#pragma unroll
        for (int j = 0; j < 8; ++j) {
            int cc = (colBase + warpN * 64 + j * 8 + (lane & 3) * 2) >> 1;
#pragma unroll
            for (int t = 0; t < 2; ++t) {
                int r = r0 + t * 8;
                float vre = acc[i][j][2 * t], vim = acc[i][j][2 * t + 1];
                if (mode == 0) {
                    int s = r >> 2, bb = r & 3;
                    if (cc < 2048) {
                        int h = cc >> 7, m = cc & 127;
                        __half* d = g_qp + ((size_t)(bb * 16 + h) * 1024 + s) * 256;
                        d[m] = __float2half(vre); d[128 + m] = __float2half(vim);
                    } else if (cc < 4096) {
                        int u = cc - 2048, h = u >> 7, m = u & 127;
                        __half* d = g_kp + ((size_t)(bb * 16 + h) * 1024 + s) * 256;
                        d[m] = __float2half(vre); d[128 + m] = __float2half(vim);
                    } else {
                        int u = cc - 4096, h = u >> 6, vc = u & 63;
                        __half* d = g_vt + (size_t)(bb * 16 + h) * 128 * 1024;
                        d[(size_t)vc * 1024 + s]        = __float2half(vre);
                        d[(size_t)(64 + vc) * 1024 + s] = __float2half(vim);
                    }
                } else {
                    size_t i0 = (size_t)r * 1024 + cc;
                    Dout[i0]       = vre + xre[i0];
                    Dout[SBE + i0] = vim + xim[i0];
                }
            }
        }
    }
}

// ---------------- HMMA flash attention ------------------------------------------
#define QPITCH 528
#define KPITCH 528
#define VPITCH 80
#define AT_SMK0 (64 * QPITCH)                 // 33792
#define AT_SMK1 (AT_SMK0 + 32 * KPITCH)
#define AT_SMV0 (AT_SMK1 + 32 * KPITCH)
#define AT_SMV1 (AT_SMV0 + 128 * VPITCH)
#define AT_TOT  (AT_SMV1 + 128 * VPITCH)      // 88064

__device__ __forceinline__ void load_kv(uint32_t smb, int buf,
    const __half* Kg, const __half* Vg, int kt, int tid)
{
    uint32_t kdst = smb + (buf ? AT_SMK1 : AT_SMK0);
    const __half* ksrc = Kg + (size_t)kt * 32 * 256;
#pragma unroll
    for (int i = 0; i < 8; ++i) {
        int c = tid + i * 128, row = c >> 5, seg = c & 31;
        cp_async16(kdst + row * KPITCH + seg * 16, ksrc + (size_t)row * 256 + seg * 8);
    }
    uint32_t vdst = smb + (buf ? AT_SMV1 : AT_SMV0);
#pragma unroll
    for (int i = 0; i < 4; ++i) {
        int c = tid + i * 128, vc = c >> 2, seg = c & 3;
        cp_async16(vdst + vc * VPITCH + seg * 16,
                   Vg + (size_t)vc * 1024 + kt * 32 + seg * 8);
    }
}

__global__ __launch_bounds__(128) void attn_mma()
{
    extern __shared__ char sm[];
    const uint32_t smb = smem_u32(sm);
    const int tid = threadIdx.x, lane = tid & 31, wid = tid >> 5;
    const int qt = 15 - blockIdx.x;
    const int bh = blockIdx.y;
    const int qbase = qt * 64;
    const int nkt = 2 * qt + 2;
    const float scale = 0.088388347648318447f;

    const __half* Qg = g_qp + ((size_t)bh * 1024 + qbase) * 256;
    const __half* Kg = g_kp + (size_t)bh * 1024 * 256;
    const __half* Vg = g_vt + (size_t)bh * 128 * 1024;

#pragma unroll
    for (int i = 0; i < 16; ++i) {
        int c = tid + i * 128, row = c >> 5, seg = c & 31;
        cp_async16(smb + row * QPITCH + seg * 16, Qg + (size_t)row * 256 + seg * 8);
    }
    load_kv(smb, 0, Kg, Vg, 0, tid);
    CP_COMMIT();

    float m0 = -1e30f, m1 = -1e30f, l0 = 0.f, l1 = 0.f;
    float accR[8][4], accI[8][4];
#pragma unroll
    for (int j = 0; j < 8; ++j)
#pragma unroll
        for (int k = 0; k < 4; ++k) { accR[j][k] = 0.f; accI[j][k] = 0.f; }

    const int rowg = qbase + wid * 16 + (lane >> 2);
    const uint32_t aBase = smb + (wid * 16 + (lane & 15)) * QPITCH + (lane >> 4) * 16;

#pragma unroll 1
    for (int kt = 0; kt < nkt; ++kt) {
        if (kt + 1 < nkt) { load_kv(smb, (kt + 1) & 1, Kg, Vg, kt + 1, tid); CP_COMMIT(); CP_WAIT1(); }
        else CP_WAIT0();
        __syncthreads();
        const uint32_t kbuf = smb + ((kt & 1) ? AT_SMK1 : AT_SMK0);
        const uint32_t vbuf = smb + ((kt & 1) ? AT_SMV1 : AT_SMV0);

        float S[4][4][4];
#pragma unroll
        for (int c2 = 0; c2 < 4; ++c2)
#pragma unroll
            for (int n = 0; n < 4; ++n)
#pragma unroll
                for (int q = 0; q < 4; ++q) S[c2][n][q] = 0.f;

        // QK^T: rr,ii,ri,ir; everything unsplit -> 4 mma per (ks, nt)
#pragma unroll
        for (int ks = 0; ks < 8; ++ks) {
            uint32_t ar[4], ai[4];
            uint32_t aa = aBase + ks * 32;
            ldsm_x4(ar[0], ar[1], ar[2], ar[3], aa);
            ldsm_x4(ai[0], ai[1], ai[2], ai[3], aa + 256);
#pragma unroll
            for (int ntp = 0; ntp < 2; ++ntp) {
                uint32_t ba = kbuf + (ntp * 16 + (lane & 15)) * KPITCH + (lane >> 4) * 16 + ks * 32;
                uint32_t br[4], bi[4];
                ldsm_x4(br[0], br[1], br[2], br[3], ba);
                ldsm_x4(bi[0], bi[1], bi[2], bi[3], ba + 256);
#pragma unroll
                for (int t2 = 0; t2 < 2; ++t2) {
                    int nt = 2 * ntp + t2;
                    mma_f16(S[0][nt], ar, br[t2], br[t2 + 2]);
                    mma_f16(S[1][nt], ai, bi[t2], bi[t2 + 2]);
                    mma_f16(S[2][nt], ar, bi[t2], bi[t2 + 2]);
                    mma_f16(S[3][nt], ai, br[t2], br[t2 + 2]);
                }
            }
        }

        float mx0 = -1e30f, mx1 = -1e30f;
#pragma unroll
        for (int nt = 0; nt < 4; ++nt)
#pragma unroll
            for (int q = 0; q < 4; ++q) {
                float re = S[0][nt][q] - S[1][nt][q];
                float im = S[2][nt][q] + S[3][nt][q];
                float amp = famp(re, im) * scale;
                int col = kt * 32 + nt * 8 + (lane & 3) * 2 + (q & 1);
                int row = rowg + ((q >> 1) ? 8 : 0);
                float logit = (col <= row) ? amp : -1e30f;
                S[0][nt][q] = logit;
                if (q < 2) mx0 = fmaxf(mx0, logit);
                else       mx1 = fmaxf(mx1, logit);
            }
        mx0 = fmaxf(mx0, __shfl_xor_sync(~0u, mx0, 1));
        mx0 = fmaxf(mx0, __shfl_xor_sync(~0u, mx0, 2));
        mx1 = fmaxf(mx1, __shfl_xor_sync(~0u, mx1, 1));
        mx1 = fmaxf(mx1, __shfl_xor_sync(~0u, mx1, 2));
        float m0n = fmaxf(m0, mx0), m1n = fmaxf(m1, mx1);
        float corr0 = fexp(m0 - m0n), corr1 = fexp(m1 - m1n);
        float ph[4][4];
        float sum0 = 0.f, sum1 = 0.f;
#pragma unroll
        for (int nt = 0; nt < 4; ++nt)
#pragma unroll
            for (int q = 0; q < 4; ++q) {
                float p = fexp(S[0][nt][q] - ((q < 2) ? m0n : m1n));
                if (q < 2) sum0 += p; else sum1 += p;
                ph[nt][q] = p;
            }
        sum0 += __shfl_xor_sync(~0u, sum0, 1);
        sum0 += __shfl_xor_sync(~0u, sum0, 2);
        sum1 += __shfl_xor_sync(~0u, sum1, 1);
        sum1 += __shfl_xor_sync(~0u, sum1, 2);
        l0 = l0 * corr0 + sum0;
        l1 = l1 * corr1 + sum1;
        m0 = m0n; m1 = m1n;
#pragma unroll
        for (int j = 0; j < 8; ++j) {
            accR[j][0] *= corr0; accR[j][1] *= corr0;
            accR[j][2] *= corr1; accR[j][3] *= corr1;
            accI[j][0] *= corr0; accI[j][1] *= corr0;
            accI[j][2] *= corr1; accI[j][3] *= corr1;
        }

        // P*V: P unsplit -> 2 mma per (s, pr, component)
#pragma unroll
        for (int s = 0; s < 2; ++s) {
            uint32_t Ah[4];
            Ah[0] = pack_h2(ph[2 * s][0], ph[2 * s][1]);
            Ah[1] = pack_h2(ph[2 * s][2], ph[2 * s][3]);
            Ah[2] = pack_h2(ph[2 * s + 1][0], ph[2 * s + 1][1]);
            Ah[3] = pack_h2(ph[2 * s + 1][2], ph[2 * s + 1][3]);
#pragma unroll
            for (int pr = 0; pr < 4; ++pr) {
                uint32_t va = vbuf + (pr * 16 + (lane & 15)) * VPITCH + (lane >> 4) * 16 + s * 32;
                uint32_t vr[4], vi[4];
                ldsm_x4(vr[0], vr[1], vr[2], vr[3], va);
                ldsm_x4(vi[0], vi[1], vi[2], vi[3], va + 64 * VPITCH);
                mma_f16(accR[2 * pr],     Ah, vr[0], vr[2]);
                mma_f16(accR[2 * pr + 1], Ah, vr[1], vr[3]);
                mma_f16(accI[2 * pr],     Ah, vi[0], vi[2]);
                mma_f16(accI[2 * pr + 1], Ah, vi[1], vi[3]);
            }
        }
        __syncthreads();
    }

    const float inv0 = 1.0f / l0, inv1 = 1.0f / l1;
    const int b = bh >> 4, h = bh & 15;
#pragma unroll
    for (int t = 0; t < 2; ++t) {
        int srow = rowg + t * 8;
        size_t r = (size_t)srow * 4 + b;
        float inv = t ? inv1 : inv0;
#pragma unroll
        for (int j = 0; j < 8; ++j)
#pragma unroll
            for (int e2 = 0; e2 < 2; ++e2) {
                int vc = j * 8 + (lane & 3) * 2 + e2;
                float re = accR[j][2 * t + e2] * inv;
                float im = accI[j][2 * t + e2] * inv;
                __half* p = g_Aatt + r * GK + (h * 64 + vc);
                p[0] = __float2half(re);
                p[1024] = __float2half(im);
            }
    }
}

// ---------------------------------------------------------------------------
extern "C" void kernel_launch(void* const* d_in, const int* in_sizes, int n_in,
                              void* d_out, int out_size)
{
    const float* xre = (const float*)d_in[0];
    const float* xim = (const float*)d_in[1];
    float* out = (float*)d_out;

    const int gemm_smem = 4 * STAGEB;
    static bool attr_set = false;
    if (!attr_set) {
        cudaFuncSetAttribute(gemm_hmma,
                             cudaFuncAttributeMaxDynamicSharedMemorySize, gemm_smem);
        cudaFuncSetAttribute(attn_mma,
                             cudaFuncAttributeMaxDynamicSharedMemorySize, AT_TOT);
        attr_set = true;
    }

    pack_A_proj<<<16384, 256>>>(xre, xim);
    pack_B_proj<<<20480, 256>>>((const float*)d_in[2], (const float*)d_in[3],
                                (const float*)d_in[4], (const float*)d_in[5],
                                (const float*)d_in[6], (const float*)d_in[7]);
    pack_B_out<<<4096, 256>>>((const float*)d_in[8], (const float*)d_in[9]);

    gemm_hmma<<<dim3(32, 40), 512, gemm_smem>>>(0, nullptr, nullptr, nullptr);

    attn_mma<<<dim3(16, 64), 128, AT_TOT>>>();

    gemm_hmma<<<dim3(32, 8), 512, gemm_smem>>>(1, out, xre, xim);
}

// round 10
// speedup vs baseline: 6.6929x; 1.0458x over previous
#include <cuda_runtime.h>
#include <cuda_fp16.h>
#include <cstdint>
#include <math.h>

#define Ssz 1024
#define Bsz 4
#define Esz 1024
#define SBE (Ssz * Bsz * Esz)
#define GK  2048                    // 2 planes x 1024 (plain fp16)
#define NCHUNK (GK / 64)            // 32 chunks of 64

// ---------------- scratch -----------------------------------------------------
__device__ __align__(16) __half g_Aproj[4096u * GK];
__device__ __align__(16) __half g_Bproj[10240u * GK];
__device__ __align__(16) __half g_Bout [2048u * GK];
__device__ __align__(16) __half g_Aatt [4096u * GK];
__device__ __align__(16) __half g_qp[64u * 1024 * 256]; // [bh][s][qr(128)|qi(128)]
__device__ __align__(16) __half g_kp[64u * 1024 * 256]; // [bh][t][kr|ki]
__device__ __align__(16) __half g_vt[64u * 128 * 1024]; // [bh][vr(64)|vi(64) planes][t]

// ---------------- helpers ------------------------------------------------------
__device__ __forceinline__ uint32_t smem_u32(const void* p) {
    uint32_t a;
    asm("{ .reg .u64 t; cvta.to.shared.u64 t, %1; cvt.u32.u64 %0, t; }" : "=r"(a) : "l"(p));
    return a;
}
__device__ __forceinline__ void cp_async16(uint32_t dst, const void* src) {
    asm volatile("cp.async.cg.shared.global [%0], [%1], 16;" :: "r"(dst), "l"(src) : "memory");
}
#define CP_COMMIT() asm volatile("cp.async.commit_group;" ::: "memory")
#define CP_WAIT0()  asm volatile("cp.async.wait_group 0;" ::: "memory")
#define CP_WAIT1()  asm volatile("cp.async.wait_group 1;" ::: "memory")

__device__ __forceinline__ void ldsm_x4(uint32_t& r0, uint32_t& r1,
                                        uint32_t& r2, uint32_t& r3, uint32_t a) {
    asm volatile("ldmatrix.sync.aligned.m8n8.x4.shared.b16 {%0,%1,%2,%3}, [%4];"
                 : "=r"(r0), "=r"(r1), "=r"(r2), "=r"(r3) : "r"(a));
}
__device__ __forceinline__ void mma_f16(float* d, const uint32_t* a,
                                        uint32_t b0, uint32_t b1) {
    asm volatile(
        "mma.sync.aligned.m16n8k16.row.col.f32.f16.f16.f32 "
        "{%0,%1,%2,%3}, {%4,%5,%6,%7}, {%8,%9}, {%0,%1,%2,%3};"
        : "+f"(d[0]), "+f"(d[1]), "+f"(d[2]), "+f"(d[3])
        : "r"(a[0]), "r"(a[1]), "r"(a[2]), "r"(a[3]), "r"(b0), "r"(b1));
}
__device__ __forceinline__ uint32_t pack_h2(float lo, float hi) {
    uint32_t r;
    asm("cvt.rn.f16x2.f32 %0, %1, %2;" : "=r"(r) : "f"(hi), "f"(lo));
    return r;
}
// e^x for x <= ~0, FMA-pipe only (no MUFU)
__device__ __forceinline__ float fexp(float x) {
    float t = fmaxf(x * 1.4426950408889634f, -126.0f);
    int k = __float2int_rn(t);
    float f = (t - (float)k) * 0.6931471805599453f;
    float p = 1.0f + f * (1.0f + f * (0.5f + f * (0.16666667f +
                   f * (0.041666667f + f * 0.0083333333f))));
    return p * __int_as_float((k + 127) << 23);
}
// sqrt(re^2+im^2) via bit-hack rsqrt + 2 Newton iters (no MUFU)
__device__ __forceinline__ float famp(float re, float im) {
    float z = fmaf(re, re, im * im);
    z = fmaxf(z, 1e-37f);
    float r = __int_as_float(0x5f3759df - (__float_as_int(z) >> 1));
    r = r * fmaf(-0.5f * z * r, r, 1.5f);
    r = r * fmaf(-0.5f * z * r, r, 1.5f);
    return z * r;
}

// ---------------- pack kernels --------------------------------------------------
__global__ __launch_bounds__(256) void pack_A_proj(
    const float* __restrict__ xre, const float* __restrict__ xim)
{
    int idx = blockIdx.x * 256 + threadIdx.x;
    int r = idx >> 10, e = idx & 1023;
    __half* p = g_Aproj + (size_t)r * GK + e;
    p[0] = __float2half(xre[idx]);
    p[1024] = __float2half(xim[idx]);
}

// B rows: real out = [wr, -wi]; imag out = [wi, wr]
__device__ __forceinline__ void write_B_rows(__half* base, size_t n_re,
                                             int e, float wr, float wi)
{
    __half rh = __float2half(wr);
    __half ih = __float2half(wi);
    __half* pr = base + n_re * GK + e;
    pr[0] = rh; pr[1024] = __hneg(ih);
    __half* pi = base + (n_re + 1) * GK + e;
    pi[0] = ih; pi[1024] = rh;
}

__global__ __launch_bounds__(256) void pack_B_proj(
    const float* __restrict__ wq_re, const float* __restrict__ wq_im,
    const float* __restrict__ wk_re, const float* __restrict__ wk_im,
    const float* __restrict__ wv_re, const float* __restrict__ wv_im)
{
    int idx = blockIdx.x * 256 + threadIdx.x;
    int c = idx >> 10, e = idx & 1023;
    const float *wre, *wim; size_t off;
    if (c < 2048)      { wre = wq_re; wim = wq_im; off = (size_t)c * 1024 + e; }
    else if (c < 4096) { wre = wk_re; wim = wk_im; off = (size_t)(c - 2048) * 1024 + e; }
    else               { wre = wv_re; wim = wv_im; off = (size_t)(c - 4096) * 1024 + e; }
    write_B_rows(g_Bproj, (size_t)(2 * c), e, wre[off], wim[off]);
}

__global__ __launch_bounds__(256) void pack_B_out(
    const float* __restrict__ wo_re, const float* __restrict__ wo_im)
{
    int idx = blockIdx.x * 256 + threadIdx.x;
    int f = idx >> 10, e = idx & 1023;
    write_B_rows(g_Bout, (size_t)(2 * f), e,
                 wo_re[(size_t)e * 1024 + f], wo_im[(size_t)e * 1024 + f]);
}

// ---------------- HMMA GEMM (128x256 tile, K-chunk 64, 3 stages, 512 thr) ------
#define ROWB   144                  // 64 fp16 = 128B data + 16B pad (conflict-free)
#define STAGEB (384 * ROWB)         // 55296
#define BOFF   (128 * ROWB)         // 18432

__device__ __forceinline__ void load_stage(
    uint32_t smb, int stage, const __half* A, const __half* B,
    int rowBase, int colBase, int kk, int tid)
{
    uint32_t base = smb + stage * STAGEB;
#pragma unroll
    for (int i = 0; i < 2; ++i) {   // A: 128 rows x 8 segs
        int v = tid + i * 512, row = v >> 3, seg = v & 7;
        cp_async16(base + row * ROWB + seg * 16,
                   A + (size_t)(rowBase + row) * GK + kk + seg * 8);
    }
#pragma unroll
    for (int i = 0; i < 4; ++i) {   // B: 256 rows x 8 segs
        int v = tid + i * 512, row = v >> 3, seg = v & 7;
        cp_async16(base + BOFF + row * ROWB + seg * 16,
                   B + (size_t)(colBase + row) * GK + kk + seg * 8);
    }
}

__global__ __launch_bounds__(512, 1) void gemm_hmma(
    int mode, float* __restrict__ Dout,
    const float* __restrict__ xre, const float* __restrict__ xim)
{
    extern __shared__ char sm[];
    const uint32_t smb = smem_u32(sm);
    const int tid = threadIdx.x;
    const int wid = tid >> 5, lane = tid & 31;
    const int warpM = wid >> 2, warpN = wid & 3;      // 4 x 4 warps
    const int rowBase = blockIdx.x * 128;
    const int colBase = blockIdx.y * 256;
    const __half* A = mode ? g_Aatt : g_Aproj;
    const __half* B = mode ? g_Bout : g_Bproj;

    float acc[2][8][4];                               // warp tile 32x64
#pragma unroll
    for (int i = 0; i < 2; ++i)
#pragma unroll
        for (int j = 0; j < 8; ++j)
#pragma unroll
            for (int k = 0; k < 4; ++k) acc[i][j][k] = 0.f;

    load_stage(smb, 0, A, B, rowBase, colBase, 0, tid);  CP_COMMIT();
    load_stage(smb, 1, A, B, rowBase, colBase, 64, tid); CP_COMMIT();

    const uint32_t aRowAddr = smb + (warpM * 32 + (lane & 15)) * ROWB + (lane >> 4) * 16;
    const uint32_t bRowAddr = smb + BOFF + (warpN * 64 + (lane & 15)) * ROWB + (lane >> 4) * 16;

#pragma unroll 1
    for (int c = 0; c < NCHUNK; ++c) {
        CP_WAIT1();
        __syncthreads();
        const uint32_t stoff = (c % 3) * STAGEB;
        // issue next-next chunk immediately: overlaps the whole compute block
        if (c + 2 < NCHUNK)
            load_stage(smb, (c + 2) % 3, A, B, rowBase, colBase, (c + 2) * 64, tid);
        CP_COMMIT();
#pragma unroll
        for (int ks = 0; ks < 4; ++ks) {
            uint32_t a[2][4], b[8][2];
#pragma unroll
            for (int i = 0; i < 2; ++i)
                ldsm_x4(a[i][0], a[i][1], a[i][2], a[i][3],
                        aRowAddr + stoff + i * 16 * ROWB + ks * 32);
#pragma unroll
            for (int jj = 0; jj < 4; ++jj) {
                uint32_t r0, r1, r2, r3;
                ldsm_x4(r0, r1, r2, r3, bRowAddr + stoff + jj * 16 * ROWB + ks * 32);
                b[2 * jj][0] = r0; b[2 * jj][1] = r2;
                b[2 * jj + 1][0] = r1; b[2 * jj + 1][1] = r3;
            }
#pragma unroll
            for (int i = 0; i < 2; ++i)
#pragma unroll
                for (int j = 0; j < 8; ++j)
                    mma_f16(acc[i][j], a[i], b[j][0], b[j][1]);
        }
    }

    const int lrow = lane >> 2;
#pragma unroll
    for (int i = 0; i < 2; ++i) {
        int r0 = rowBase + warpM * 32 + i * 16 + lrow;
#pragma unroll
        for (int j = 0; j < 8; ++j) {
            int cc = (colBase + warpN * 64 + j * 8 + (lane & 3) * 2) >> 1;
#pragma unroll
            for (int t = 0; t < 2; ++t) {
                int r = r0 + t * 8;
                float vre = acc[i][j][2 * t], vim = acc[i][j][2 * t + 1];
                if (mode == 0) {
                    int s = r >> 2, bb = r & 3;
                    if (cc < 2048) {
                        int h = cc >> 7, m = cc & 127;
                        __half* d = g_qp + ((size_t)(bb * 16 + h) * 1024 + s) * 256;
                        d[m] = __float2half(vre); d[128 + m] = __float2half(vim);
                    } else if (cc < 4096) {
                        int u = cc - 2048, h = u >> 7, m = u & 127;
                        __half* d = g_kp + ((size_t)(bb * 16 + h) * 1024 + s) * 256;
                        d[m] = __float2half(vre); d[128 + m] = __float2half(vim);
                    } else {
                        int u = cc - 4096, h = u >> 6, vc = u & 63;
                        __half* d = g_vt + (size_t)(bb * 16 + h) * 128 * 1024;
                        d[(size_t)vc * 1024 + s]        = __float2half(vre);
                        d[(size_t)(64 + vc) * 1024 + s] = __float2half(vim);
                    }
                } else {
                    size_t i0 = (size_t)r * 1024 + cc;
                    Dout[i0]       = vre + xre[i0];
                    Dout[SBE + i0] = vim + xim[i0];
                }
            }
        }
    }
}

// ---------------- HMMA flash attention (unchanged from R9) ----------------------
#define QPITCH 528
#define KPITCH 528
#define VPITCH 80
#define AT_SMK0 (64 * QPITCH)
#define AT_SMK1 (AT_SMK0 + 32 * KPITCH)
#define AT_SMV0 (AT_SMK1 + 32 * KPITCH)
#define AT_SMV1 (AT_SMV0 + 128 * VPITCH)
#define AT_TOT  (AT_SMV1 + 128 * VPITCH)

__device__ __forceinline__ void load_kv(uint32_t smb, int buf,
    const __half* Kg, const __half* Vg, int kt, int tid)
{
    uint32_t kdst = smb + (buf ? AT_SMK1 : AT_SMK0);
    const __half* ksrc = Kg + (size_t)kt * 32 * 256;
#pragma unroll
    for (int i = 0; i < 8; ++i) {
        int c = tid + i * 128, row = c >> 5, seg = c & 31;
        cp_async16(kdst + row * KPITCH + seg * 16, ksrc + (size_t)row * 256 + seg * 8);
    }
    uint32_t vdst = smb + (buf ? AT_SMV1 : AT_SMV0);
#pragma unroll
    for (int i = 0; i < 4; ++i) {
        int c = tid + i * 128, vc = c >> 2, seg = c & 3;
        cp_async16(vdst + vc * VPITCH + seg * 16,
                   Vg + (size_t)vc * 1024 + kt * 32 + seg * 8);
    }
}

__global__ __launch_bounds__(128) void attn_mma()
{
    extern __shared__ char sm[];
    const uint32_t smb = smem_u32(sm);
    const int tid = threadIdx.x, lane = tid & 31, wid = tid >> 5;
    const int qt = 15 - blockIdx.x;
    const int bh = blockIdx.y;
    const int qbase = qt * 64;
    const int nkt = 2 * qt + 2;
    const float scale = 0.088388347648318447f;

    const __half* Qg = g_qp + ((size_t)bh * 1024 + qbase) * 256;
    const __half* Kg = g_kp + (size_t)bh * 1024 * 256;
    const __half* Vg = g_vt + (size_t)bh * 128 * 1024;

#pragma unroll
    for (int i = 0; i < 16; ++i) {
        int c = tid + i * 128, row = c >> 5, seg = c & 31;
        cp_async16(smb + row * QPITCH + seg * 16, Qg + (size_t)row * 256 + seg * 8);
    }
    load_kv(smb, 0, Kg, Vg, 0, tid);
    CP_COMMIT();

    float m0 = -1e30f, m1 = -1e30f, l0 = 0.f, l1 = 0.f;
    float accR[8][4], accI[8][4];
#pragma unroll
    for (int j = 0; j < 8; ++j)
#pragma unroll
        for (int k = 0; k < 4; ++k) { accR[j][k] = 0.f; accI[j][k] = 0.f; }

    const int rowg = qbase + wid * 16 + (lane >> 2);
    const uint32_t aBase = smb + (wid * 16 + (lane & 15)) * QPITCH + (lane >> 4) * 16;

#pragma unroll 1
    for (int kt = 0; kt < nkt; ++kt) {
        if (kt + 1 < nkt) { load_kv(smb, (kt + 1) & 1, Kg, Vg, kt + 1, tid); CP_COMMIT(); CP_WAIT1(); }
        else CP_WAIT0();
        __syncthreads();
        const uint32_t kbuf = smb + ((kt & 1) ? AT_SMK1 : AT_SMK0);
        const uint32_t vbuf = smb + ((kt & 1) ? AT_SMV1 : AT_SMV0);

        float S[4][4][4];
#pragma unroll
        for (int c2 = 0; c2 < 4; ++c2)
#pragma unroll
            for (int n = 0; n < 4; ++n)
#pragma unroll
                for (int q = 0; q < 4; ++q) S[c2][n][q] = 0.f;

#pragma unroll
        for (int ks = 0; ks < 8; ++ks) {
            uint32_t ar[4], ai[4];
            uint32_t aa = aBase + ks * 32;
            ldsm_x4(ar[0], ar[1], ar[2], ar[3], aa);
            ldsm_x4(ai[0], ai[1], ai[2], ai[3], aa + 256);
#pragma unroll
            for (int ntp = 0; ntp < 2; ++ntp) {
                uint32_t ba = kbuf + (ntp * 16 + (lane & 15)) * KPITCH + (lane >> 4) * 16 + ks * 32;
                uint32_t br[4], bi[4];
                ldsm_x4(br[0], br[1], br[2], br[3], ba);
                ldsm_x4(bi[0], bi[1], bi[2], bi[3], ba + 256);
#pragma unroll
                for (int t2 = 0; t2 < 2; ++t2) {
                    int nt = 2 * ntp + t2;
                    mma_f16(S[0][nt], ar, br[t2], br[t2 + 2]);
                    mma_f16(S[1][nt], ai, bi[t2], bi[t2 + 2]);
                    mma_f16(S[2][nt], ar, bi[t2], bi[t2 + 2]);
                    mma_f16(S[3][nt], ai, br[t2], br[t2 + 2]);
                }
            }
        }

        float mx0 = -1e30f, mx1 = -1e30f;
#pragma unroll
        for (int nt = 0; nt < 4; ++nt)
#pragma unroll
            for (int q = 0; q < 4; ++q) {
                float re = S[0][nt][q] - S[1][nt][q];
                float im = S[2][nt][q] + S[3][nt][q];
                float amp = famp(re, im) * scale;
                int col = kt * 32 + nt * 8 + (lane & 3) * 2 + (q & 1);
                int row = rowg + ((q >> 1) ? 8 : 0);
                float logit = (col <= row) ? amp : -1e30f;
                S[0][nt][q] = logit;
                if (q < 2) mx0 = fmaxf(mx0, logit);
                else       mx1 = fmaxf(mx1, logit);
            }
        mx0 = fmaxf(mx0, __shfl_xor_sync(~0u, mx0, 1));
        mx0 = fmaxf(mx0, __shfl_xor_sync(~0u, mx0, 2));
        mx1 = fmaxf(mx1, __shfl_xor_sync(~0u, mx1, 1));
        mx1 = fmaxf(mx1, __shfl_xor_sync(~0u, mx1, 2));
        float m0n = fmaxf(m0, mx0), m1n = fmaxf(m1, mx1);
        float corr0 = fexp(m0 - m0n), corr1 = fexp(m1 - m1n);
        float ph[4][4];
        float sum0 = 0.f, sum1 = 0.f;
#pragma unroll
        for (int nt = 0; nt < 4; ++nt)
#pragma unroll
            for (int q = 0; q < 4; ++q) {
                float p = fexp(S[0][nt][q] - ((q < 2) ? m0n : m1n));
                if (q < 2) sum0 += p; else sum1 += p;
                ph[nt][q] = p;
            }
        sum0 += __shfl_xor_sync(~0u, sum0, 1);
        sum0 += __shfl_xor_sync(~0u, sum0, 2);
        sum1 += __shfl_xor_sync(~0u, sum1, 1);
        sum1 += __shfl_xor_sync(~0u, sum1, 2);
        l0 = l0 * corr0 + sum0;
        l1 = l1 * corr1 + sum1;
        m0 = m0n; m1 = m1n;
#pragma unroll
        for (int j = 0; j < 8; ++j) {
            accR[j][0] *= corr0; accR[j][1] *= corr0;
            accR[j][2] *= corr1; accR[j][3] *= corr1;
            accI[j][0] *= corr0; accI[j][1] *= corr0;
            accI[j][2] *= corr1; accI[j][3] *= corr1;
        }

#pragma unroll
        for (int s = 0; s < 2; ++s) {
            uint32_t Ah[4];
            Ah[0] = pack_h2(ph[2 * s][0], ph[2 * s][1]);
            Ah[1] = pack_h2(ph[2 * s][2], ph[2 * s][3]);
            Ah[2] = pack_h2(ph[2 * s + 1][0], ph[2 * s + 1][1]);
            Ah[3] = pack_h2(ph[2 * s + 1][2], ph[2 * s + 1][3]);
#pragma unroll
            for (int pr = 0; pr < 4; ++pr) {
                uint32_t va = vbuf + (pr * 16 + (lane & 15)) * VPITCH + (lane >> 4) * 16 + s * 32;
                uint32_t vr[4], vi[4];
                ldsm_x4(vr[0], vr[1], vr[2], vr[3], va);
                ldsm_x4(vi[0], vi[1], vi[2], vi[3], va + 64 * VPITCH);
                mma_f16(accR[2 * pr],     Ah, vr[0], vr[2]);
                mma_f16(accR[2 * pr + 1], Ah, vr[1], vr[3]);
                mma_f16(accI[2 * pr],     Ah, vi[0], vi[2]);
                mma_f16(accI[2 * pr + 1], Ah, vi[1], vi[3]);
            }
        }
        __syncthreads();
    }

    const float inv0 = 1.0f / l0, inv1 = 1.0f / l1;
    const int b = bh >> 4, h = bh & 15;
#pragma unroll
    for (int t = 0; t < 2; ++t) {
        int srow = rowg + t * 8;
        size_t r = (size_t)srow * 4 + b;
        float inv = t ? inv1 : inv0;
#pragma unroll
        for (int j = 0; j < 8; ++j)
#pragma unroll
            for (int e2 = 0; e2 < 2; ++e2) {
                int vc = j * 8 + (lane & 3) * 2 + e2;
                float re = accR[j][2 * t + e2] * inv;
                float im = accI[j][2 * t + e2] * inv;
                __half* p = g_Aatt + r * GK + (h * 64 + vc);
                p[0] = __float2half(re);
                p[1024] = __float2half(im);
            }
    }
}

// ---------------------------------------------------------------------------
extern "C" void kernel_launch(void* const* d_in, const int* in_sizes, int n_in,
                              void* d_out, int out_size)
{
    const float* xre = (const float*)d_in[0];
    const float* xim = (const float*)d_in[1];
    float* out = (float*)d_out;

    const int gemm_smem = 3 * STAGEB;                 // 165888
    static bool attr_set = false;
    if (!attr_set) {
        cudaFuncSetAttribute(gemm_hmma,
                             cudaFuncAttributeMaxDynamicSharedMemorySize, gemm_smem);
        cudaFuncSetAttribute(attn_mma,
                             cudaFuncAttributeMaxDynamicSharedMemorySize, AT_TOT);
        attr_set = true;
    }

    pack_A_proj<<<16384, 256>>>(xre, xim);
    pack_B_proj<<<20480, 256>>>((const float*)d_in[2], (const float*)d_in[3],
                                (const float*)d_in[4], (const float*)d_in[5],
                                (const float*)d_in[6], (const float*)d_in[7]);
    pack_B_out<<<4096, 256>>>((const float*)d_in[8], (const float*)d_in[9]);

    gemm_hmma<<<dim3(32, 40), 512, gemm_smem>>>(0, nullptr, nullptr, nullptr);

    attn_mma<<<dim3(16, 64), 128, AT_TOT>>>();

    gemm_hmma<<<dim3(32, 8), 512, gemm_smem>>>(1, out, xre, xim);
}

// round 11
// speedup vs baseline: 6.9014x; 1.0311x over previous
#include <cuda_runtime.h>
#include <cuda_fp16.h>
#include <cstdint>
#include <math.h>

#define Ssz 1024
#define Bsz 4
#define Esz 1024
#define SBE (Ssz * Bsz * Esz)
#define GK  2048                    // 2 planes x 1024 (plain fp16)
#define NCHUNK (GK / 64)            // 32 chunks of 64

// ---------------- scratch -----------------------------------------------------
__device__ __align__(16) __half g_Aproj[4096u * GK];
__device__ __align__(16) __half g_Bproj[10240u * GK];
__device__ __align__(16) __half g_Bout [2048u * GK];
__device__ __align__(16) __half g_Aatt [4096u * GK];
__device__ __align__(16) __half g_qp[64u * 1024 * 256]; // [bh][s][qr(128)|qi(128)]
__device__ __align__(16) __half g_kp[64u * 1024 * 256]; // [bh][t][kr|ki]
__device__ __align__(16) __half g_vt[64u * 128 * 1024]; // [bh][vr(64)|vi(64) planes][t]

// ---------------- helpers ------------------------------------------------------
__device__ __forceinline__ uint32_t smem_u32(const void* p) {
    uint32_t a;
    asm("{ .reg .u64 t; cvta.to.shared.u64 t, %1; cvt.u32.u64 %0, t; }" : "=r"(a) : "l"(p));
    return a;
}
__device__ __forceinline__ void cp_async16(uint32_t dst, const void* src) {
    asm volatile("cp.async.cg.shared.global [%0], [%1], 16;" :: "r"(dst), "l"(src) : "memory");
}
#define CP_COMMIT() asm volatile("cp.async.commit_group;" ::: "memory")
#define CP_WAIT0()  asm volatile("cp.async.wait_group 0;" ::: "memory")
#define CP_WAIT1()  asm volatile("cp.async.wait_group 1;" ::: "memory")

__device__ __forceinline__ void ldsm_x4(uint32_t& r0, uint32_t& r1,
                                        uint32_t& r2, uint32_t& r3, uint32_t a) {
    asm volatile("ldmatrix.sync.aligned.m8n8.x4.shared.b16 {%0,%1,%2,%3}, [%4];"
                 : "=r"(r0), "=r"(r1), "=r"(r2), "=r"(r3) : "r"(a));
}
__device__ __forceinline__ void mma_f16(float* d, const uint32_t* a,
                                        uint32_t b0, uint32_t b1) {
    asm volatile(
        "mma.sync.aligned.m16n8k16.row.col.f32.f16.f16.f32 "
        "{%0,%1,%2,%3}, {%4,%5,%6,%7}, {%8,%9}, {%0,%1,%2,%3};"
        : "+f"(d[0]), "+f"(d[1]), "+f"(d[2]), "+f"(d[3])
        : "r"(a[0]), "r"(a[1]), "r"(a[2]), "r"(a[3]), "r"(b0), "r"(b1));
}
__device__ __forceinline__ uint32_t pack_h2(float lo, float hi) {
    uint32_t r;
    asm("cvt.rn.f16x2.f32 %0, %1, %2;" : "=r"(r) : "f"(hi), "f"(lo));
    return r;
}
// e^x for x <= ~0, FMA-pipe only (no MUFU)
__device__ __forceinline__ float fexp(float x) {
    float t = fmaxf(x * 1.4426950408889634f, -126.0f);
    int k = __float2int_rn(t);
    float f = (t - (float)k) * 0.6931471805599453f;
    float p = 1.0f + f * (1.0f + f * (0.5f + f * (0.16666667f +
                   f * (0.041666667f + f * 0.0083333333f))));
    return p * __int_as_float((k + 127) << 23);
}
// sqrt(re^2+im^2) via bit-hack rsqrt + 2 Newton iters (no MUFU)
__device__ __forceinline__ float famp(float re, float im) {
    float z = fmaf(re, re, im * im);
    z = fmaxf(z, 1e-37f);
    float r = __int_as_float(0x5f3759df - (__float_as_int(z) >> 1));
    r = r * fmaf(-0.5f * z * r, r, 1.5f);
    r = r * fmaf(-0.5f * z * r, r, 1.5f);
    return z * r;
}

// ---------------- pack kernels --------------------------------------------------
__global__ __launch_bounds__(256) void pack_A_proj(
    const float* __restrict__ xre, const float* __restrict__ xim)
{
    int idx = blockIdx.x * 256 + threadIdx.x;
    int r = idx >> 10, e = idx & 1023;
    __half* p = g_Aproj + (size_t)r * GK + e;
    p[0] = __float2half(xre[idx]);
    p[1024] = __float2half(xim[idx]);
}

// B rows: real out = [wr, -wi]; imag out = [wi, wr]
__device__ __forceinline__ void write_B_rows(__half* base, size_t n_re,
                                             int e, float wr, float wi)
{
    __half rh = __float2half(wr);
    __half ih = __float2half(wi);
    __half* pr = base + n_re * GK + e;
    pr[0] = rh; pr[1024] = __hneg(ih);
    __half* pi = base + (n_re + 1) * GK + e;
    pi[0] = ih; pi[1024] = rh;
}

__global__ __launch_bounds__(256) void pack_B_proj(
    const float* __restrict__ wq_re, const float* __restrict__ wq_im,
    const float* __restrict__ wk_re, const float* __restrict__ wk_im,
    const float* __restrict__ wv_re, const float* __restrict__ wv_im)
{
    int idx = blockIdx.x * 256 + threadIdx.x;
    int c = idx >> 10, e = idx & 1023;
    const float *wre, *wim; size_t off;
    if (c < 2048)      { wre = wq_re; wim = wq_im; off = (size_t)c * 1024 + e; }
    else if (c < 4096) { wre = wk_re; wim = wk_im; off = (size_t)(c - 2048) * 1024 + e; }
    else               { wre = wv_re; wim = wv_im; off = (size_t)(c - 4096) * 1024 + e; }
    write_B_rows(g_Bproj, (size_t)(2 * c), e, wre[off], wim[off]);
}

__global__ __launch_bounds__(256) void pack_B_out(
    const float* __restrict__ wo_re, const float* __restrict__ wo_im)
{
    int idx = blockIdx.x * 256 + threadIdx.x;
    int f = idx >> 10, e = idx & 1023;
    write_B_rows(g_Bout, (size_t)(2 * f), e,
                 wo_re[(size_t)e * 1024 + f], wo_im[(size_t)e * 1024 + f]);
}

// ---------------- HMMA GEMM (128x128 tile, K-chunk 64, 2 stages, 256 thr, 2 CTA/SM)
#define ROWB   144                  // 64 fp16 = 128B data + 16B pad (conflict-free)
#define STAGEB (256 * ROWB)         // 36864: A(128 rows) + B(128 rows)
#define BOFF   (128 * ROWB)

__device__ __forceinline__ void load_stage(
    uint32_t smb, int stage, const __half* A, const __half* B,
    int rowBase, int colBase, int kk, int tid)
{
    uint32_t base = smb + stage * STAGEB;
#pragma unroll
    for (int i = 0; i < 4; ++i) {   // A: 128 rows x 8 segs = 1024 ops
        int v = tid + i * 256, row = v >> 3, seg = v & 7;
        cp_async16(base + row * ROWB + seg * 16,
                   A + (size_t)(rowBase + row) * GK + kk + seg * 8);
    }
#pragma unroll
    for (int i = 0; i < 4; ++i) {   // B: 128 rows x 8 segs
        int v = tid + i * 256, row = v >> 3, seg = v & 7;
        cp_async16(base + BOFF + row * ROWB + seg * 16,
                   B + (size_t)(colBase + row) * GK + kk + seg * 8);
    }
}

__global__ __launch_bounds__(256, 2) void gemm_hmma(
    int mode, float* __restrict__ Dout,
    const float* __restrict__ xre, const float* __restrict__ xim)
{
    extern __shared__ char sm[];
    const uint32_t smb = smem_u32(sm);
    const int tid = threadIdx.x;
    const int wid = tid >> 5, lane = tid & 31;
    const int warpM = wid >> 1, warpN = wid & 1;      // 4 x 2 warps, warp tile 32x64
    const int rowBase = blockIdx.x * 128;
    const int colBase = blockIdx.y * 128;
    const __half* A = mode ? g_Aatt : g_Aproj;
    const __half* B = mode ? g_Bout : g_Bproj;

    float acc[2][8][4];
#pragma unroll
    for (int i = 0; i < 2; ++i)
#pragma unroll
        for (int j = 0; j < 8; ++j)
#pragma unroll
            for (int k = 0; k < 4; ++k) acc[i][j][k] = 0.f;

    load_stage(smb, 0, A, B, rowBase, colBase, 0, tid);  CP_COMMIT();
    load_stage(smb, 1, A, B, rowBase, colBase, 64, tid); CP_COMMIT();

    const uint32_t aRowAddr = smb + (warpM * 32 + (lane & 15)) * ROWB + (lane >> 4) * 16;
    const uint32_t bRowAddr = smb + BOFF + (warpN * 64 + (lane & 15)) * ROWB + (lane >> 4) * 16;

#pragma unroll 1
    for (int c = 0; c < NCHUNK; ++c) {
        CP_WAIT1();
        __syncthreads();
        const uint32_t stoff = (c & 1) * STAGEB;
#pragma unroll
        for (int ks = 0; ks < 4; ++ks) {
            uint32_t a[2][4], b[8][2];
#pragma unroll
            for (int i = 0; i < 2; ++i)
                ldsm_x4(a[i][0], a[i][1], a[i][2], a[i][3],
                        aRowAddr + stoff + i * 16 * ROWB + ks * 32);
#pragma unroll
            for (int jj = 0; jj < 4; ++jj) {
                uint32_t r0, r1, r2, r3;
                ldsm_x4(r0, r1, r2, r3, bRowAddr + stoff + jj * 16 * ROWB + ks * 32);
                b[2 * jj][0] = r0; b[2 * jj][1] = r2;
                b[2 * jj + 1][0] = r1; b[2 * jj + 1][1] = r3;
            }
#pragma unroll
            for (int i = 0; i < 2; ++i)
#pragma unroll
                for (int j = 0; j < 8; ++j)
                    mma_f16(acc[i][j], a[i], b[j][0], b[j][1]);
        }
        __syncthreads();            // all warps done reading buf (c&1)
        if (c + 2 < NCHUNK)
            load_stage(smb, c & 1, A, B, rowBase, colBase, (c + 2) * 64, tid);
        CP_COMMIT();
    }

    const int lrow = lane >> 2;
#pragma unroll
    for (int i = 0; i < 2; ++i) {
        int r0 = rowBase + warpM * 32 + i * 16 + lrow;
#pragma unroll
        for (int j = 0; j < 8; ++j) {
            int cc = (colBase + warpN * 64 + j * 8 + (lane & 3) * 2) >> 1;
#pragma unroll
            for (int t = 0; t < 2; ++t) {
                int r = r0 + t * 8;
                float vre = acc[i][j][2 * t], vim = acc[i][j][2 * t + 1];
                if (mode == 0) {
                    int s = r >> 2, bb = r & 3;
                    if (cc < 2048) {
                        int h = cc >> 7, m = cc & 127;
                        __half* d = g_qp + ((size_t)(bb * 16 + h) * 1024 + s) * 256;
                        d[m] = __float2half(vre); d[128 + m] = __float2half(vim);
                    } else if (cc < 4096) {
                        int u = cc - 2048, h = u >> 7, m = u & 127;
                        __half* d = g_kp + ((size_t)(bb * 16 + h) * 1024 + s) * 256;
                        d[m] = __float2half(vre); d[128 + m] = __float2half(vim);
                    } else {
                        int u = cc - 4096, h = u >> 6, vc = u & 63;
                        __half* d = g_vt + (size_t)(bb * 16 + h) * 128 * 1024;
                        d[(size_t)vc * 1024 + s]        = __float2half(vre);
                        d[(size_t)(64 + vc) * 1024 + s] = __float2half(vim);
                    }
                } else {
                    size_t i0 = (size_t)r * 1024 + cc;
                    Dout[i0]       = vre + xre[i0];
                    Dout[SBE + i0] = vim + xim[i0];
                }
            }
        }
    }
}

// ---------------- HMMA flash attention (unchanged from R9) ----------------------
#define QPITCH 528
#define KPITCH 528
#define VPITCH 80
#define AT_SMK0 (64 * QPITCH)
#define AT_SMK1 (AT_SMK0 + 32 * KPITCH)
#define AT_SMV0 (AT_SMK1 + 32 * KPITCH)
#define AT_SMV1 (AT_SMV0 + 128 * VPITCH)
#define AT_TOT  (AT_SMV1 + 128 * VPITCH)

__device__ __forceinline__ void load_kv(uint32_t smb, int buf,
    const __half* Kg, const __half* Vg, int kt, int tid)
{
    uint32_t kdst = smb + (buf ? AT_SMK1 : AT_SMK0);
    const __half* ksrc = Kg + (size_t)kt * 32 * 256;
#pragma unroll
    for (int i = 0; i < 8; ++i) {
        int c = tid + i * 128, row = c >> 5, seg = c & 31;
        cp_async16(kdst + row * KPITCH + seg * 16, ksrc + (size_t)row * 256 + seg * 8);
    }
    uint32_t vdst = smb + (buf ? AT_SMV1 : AT_SMV0);
#pragma unroll
    for (int i = 0; i < 4; ++i) {
        int c = tid + i * 128, vc = c >> 2, seg = c & 3;
        cp_async16(vdst + vc * VPITCH + seg * 16,
                   Vg + (size_t)vc * 1024 + kt * 32 + seg * 8);
    }
}

__global__ __launch_bounds__(128) void attn_mma()
{
    extern __shared__ char sm[];
    const uint32_t smb = smem_u32(sm);
    const int tid = threadIdx.x, lane = tid & 31, wid = tid >> 5;
    const int qt = 15 - blockIdx.x;
    const int bh = blockIdx.y;
    const int qbase = qt * 64;
    const int nkt = 2 * qt + 2;
    const float scale = 0.088388347648318447f;

    const __half* Qg = g_qp + ((size_t)bh * 1024 + qbase) * 256;
    const __half* Kg = g_kp + (size_t)bh * 1024 * 256;
    const __half* Vg = g_vt + (size_t)bh * 128 * 1024;

#pragma unroll
    for (int i = 0; i < 16; ++i) {
        int c = tid + i * 128, row = c >> 5, seg = c & 31;
        cp_async16(smb + row * QPITCH + seg * 16, Qg + (size_t)row * 256 + seg * 8);
    }
    load_kv(smb, 0, Kg, Vg, 0, tid);
    CP_COMMIT();

    float m0 = -1e30f, m1 = -1e30f, l0 = 0.f, l1 = 0.f;
    float accR[8][4], accI[8][4];
#pragma unroll
    for (int j = 0; j < 8; ++j)
#pragma unroll
        for (int k = 0; k < 4; ++k) { accR[j][k] = 0.f; accI[j][k] = 0.f; }

    const int rowg = qbase + wid * 16 + (lane >> 2);
    const uint32_t aBase = smb + (wid * 16 + (lane & 15)) * QPITCH + (lane >> 4) * 16;

#pragma unroll 1
    for (int kt = 0; kt < nkt; ++kt) {
        if (kt + 1 < nkt) { load_kv(smb, (kt + 1) & 1, Kg, Vg, kt + 1, tid); CP_COMMIT(); CP_WAIT1(); }
        else CP_WAIT0();
        __syncthreads();
        const uint32_t kbuf = smb + ((kt & 1) ? AT_SMK1 : AT_SMK0);
        const uint32_t vbuf = smb + ((kt & 1) ? AT_SMV1 : AT_SMV0);

        float S[4][4][4];
#pragma unroll
        for (int c2 = 0; c2 < 4; ++c2)
#pragma unroll
            for (int n = 0; n < 4; ++n)
#pragma unroll
                for (int q = 0; q < 4; ++q) S[c2][n][q] = 0.f;

#pragma unroll
        for (int ks = 0; ks < 8; ++ks) {
            uint32_t ar[4], ai[4];
            uint32_t aa = aBase + ks * 32;
            ldsm_x4(ar[0], ar[1], ar[2], ar[3], aa);
            ldsm_x4(ai[0], ai[1], ai[2], ai[3], aa + 256);
#pragma unroll
            for (int ntp = 0; ntp < 2; ++ntp) {
                uint32_t ba = kbuf + (ntp * 16 + (lane & 15)) * KPITCH + (lane >> 4) * 16 + ks * 32;
                uint32_t br[4], bi[4];
                ldsm_x4(br[0], br[1], br[2], br[3], ba);
                ldsm_x4(bi[0], bi[1], bi[2], bi[3], ba + 256);
#pragma unroll
                for (int t2 = 0; t2 < 2; ++t2) {
                    int nt = 2 * ntp + t2;
                    mma_f16(S[0][nt], ar, br[t2], br[t2 + 2]);
                    mma_f16(S[1][nt], ai, bi[t2], bi[t2 + 2]);
                    mma_f16(S[2][nt], ar, bi[t2], bi[t2 + 2]);
                    mma_f16(S[3][nt], ai, br[t2], br[t2 + 2]);
                }
            }
        }

        float mx0 = -1e30f, mx1 = -1e30f;
#pragma unroll
        for (int nt = 0; nt < 4; ++nt)
#pragma unroll
            for (int q = 0; q < 4; ++q) {
                float re = S[0][nt][q] - S[1][nt][q];
                float im = S[2][nt][q] + S[3][nt][q];
                float amp = famp(re, im) * scale;
                int col = kt * 32 + nt * 8 + (lane & 3) * 2 + (q & 1);
                int row = rowg + ((q >> 1) ? 8 : 0);
                float logit = (col <= row) ? amp : -1e30f;
                S[0][nt][q] = logit;
                if (q < 2) mx0 = fmaxf(mx0, logit);
                else       mx1 = fmaxf(mx1, logit);
            }
        mx0 = fmaxf(mx0, __shfl_xor_sync(~0u, mx0, 1));
        mx0 = fmaxf(mx0, __shfl_xor_sync(~0u, mx0, 2));
        mx1 = fmaxf(mx1, __shfl_xor_sync(~0u, mx1, 1));
        mx1 = fmaxf(mx1, __shfl_xor_sync(~0u, mx1, 2));
        float m0n = fmaxf(m0, mx0), m1n = fmaxf(m1, mx1);
        float corr0 = fexp(m0 - m0n), corr1 = fexp(m1 - m1n);
        float ph[4][4];
        float sum0 = 0.f, sum1 = 0.f;
#pragma unroll
        for (int nt = 0; nt < 4; ++nt)
#pragma unroll
            for (int q = 0; q < 4; ++q) {
                float p = fexp(S[0][nt][q] - ((q < 2) ? m0n : m1n));
                if (q < 2) sum0 += p; else sum1 += p;
                ph[nt][q] = p;
            }
        sum0 += __shfl_xor_sync(~0u, sum0, 1);
        sum0 += __shfl_xor_sync(~0u, sum0, 2);
        sum1 += __shfl_xor_sync(~0u, sum1, 1);
        sum1 += __shfl_xor_sync(~0u, sum1, 2);
        l0 = l0 * corr0 + sum0;
        l1 = l1 * corr1 + sum1;
        m0 = m0n; m1 = m1n;
#pragma unroll
        for (int j = 0; j < 8; ++j) {
            accR[j][0] *= corr0; accR[j][1] *= corr0;
            accR[j][2] *= corr1; accR[j][3] *= corr1;
            accI[j][0] *= corr0; accI[j][1] *= corr0;
            accI[j][2] *= corr1; accI[j][3] *= corr1;
        }

#pragma unroll
        for (int s = 0; s < 2; ++s) {
            uint32_t Ah[4];
            Ah[0] = pack_h2(ph[2 * s][0], ph[2 * s][1]);
            Ah[1] = pack_h2(ph[2 * s][2], ph[2 * s][3]);
            Ah[2] = pack_h2(ph[2 * s + 1][0], ph[2 * s + 1][1]);
            Ah[3] = pack_h2(ph[2 * s + 1][2], ph[2 * s + 1][3]);
#pragma unroll
            for (int pr = 0; pr < 4; ++pr) {
                uint32_t va = vbuf + (pr * 16 + (lane & 15)) * VPITCH + (lane >> 4) * 16 + s * 32;
                uint32_t vr[4], vi[4];
                ldsm_x4(vr[0], vr[1], vr[2], vr[3], va);
                ldsm_x4(vi[0], vi[1], vi[2], vi[3], va + 64 * VPITCH);
                mma_f16(accR[2 * pr],     Ah, vr[0], vr[2]);
                mma_f16(accR[2 * pr + 1], Ah, vr[1], vr[3]);
                mma_f16(accI[2 * pr],     Ah, vi[0], vi[2]);
                mma_f16(accI[2 * pr + 1], Ah, vi[1], vi[3]);
            }
        }
        __syncthreads();
    }

    const float inv0 = 1.0f / l0, inv1 = 1.0f / l1;
    const int b = bh >> 4, h = bh & 15;
#pragma unroll
    for (int t = 0; t < 2; ++t) {
        int srow = rowg + t * 8;
        size_t r = (size_t)srow * 4 + b;
        float inv = t ? inv1 : inv0;
#pragma unroll
        for (int j = 0; j < 8; ++j)
#pragma unroll
            for (int e2 = 0; e2 < 2; ++e2) {
                int vc = j * 8 + (lane & 3) * 2 + e2;
                float re = accR[j][2 * t + e2] * inv;
                float im = accI[j][2 * t + e2] * inv;
                __half* p = g_Aatt + r * GK + (h * 64 + vc);
                p[0] = __float2half(re);
                p[1024] = __float2half(im);
            }
    }
}

// ---------------------------------------------------------------------------
extern "C" void kernel_launch(void* const* d_in, const int* in_sizes, int n_in,
                              void* d_out, int out_size)
{
    const float* xre = (const float*)d_in[0];
    const float* xim = (const float*)d_in[1];
    float* out = (float*)d_out;

    const int gemm_smem = 2 * STAGEB;                 // 73728 per CTA (2 CTAs/SM)
    static bool attr_set = false;
    if (!attr_set) {
        cudaFuncSetAttribute(gemm_hmma,
                             cudaFuncAttributeMaxDynamicSharedMemorySize, gemm_smem);
        cudaFuncSetAttribute(attn_mma,
                             cudaFuncAttributeMaxDynamicSharedMemorySize, AT_TOT);
        attr_set = true;
    }

    pack_A_proj<<<16384, 256>>>(xre, xim);
    pack_B_proj<<<20480, 256>>>((const float*)d_in[2], (const float*)d_in[3],
                                (const float*)d_in[4], (const float*)d_in[5],
                                (const float*)d_in[6], (const float*)d_in[7]);
    pack_B_out<<<4096, 256>>>((const float*)d_in[8], (const float*)d_in[9]);

    gemm_hmma<<<dim3(32, 80), 256, gemm_smem>>>(0, nullptr, nullptr, nullptr);

    attn_mma<<<dim3(16, 64), 128, AT_TOT>>>();

    gemm_hmma<<<dim3(32, 16), 256, gemm_smem>>>(1, out, xre, xim);
}